// round 1
// baseline (speedup 1.0000x reference)
#include <cuda_runtime.h>
#include <math.h>

#define BB 4
#define TT 4096
#define CC 1024
#define MT (BB*TT)          // 16384 rows

// ---------------- scratch (no cudaMalloc allowed) ----------------
__device__ float g_xk[MT*CC];
__device__ float g_xv[MT*CC];
__device__ float g_xr[MT*CC];
__device__ float g_k [MT*CC];
__device__ float g_v [MT*CC];
__device__ float g_sr[MT*CC];
__device__ float g_rwkv[MT*CC];

// ---------------- 1) token-shift mix: xk/xv/xr ----------------
__global__ void __launch_bounds__(256) mix_kernel(
    const float* __restrict__ x,
    const float* __restrict__ mk,
    const float* __restrict__ mv,
    const float* __restrict__ mr)
{
    long long idx = (long long)blockIdx.x * blockDim.x + threadIdx.x;
    long long i = idx * 4;                         // float4 granularity
    if (i >= (long long)MT * CC) return;
    int c = (int)(i & (CC - 1));
    int m = (int)(i >> 10);                        // i / CC
    int t = m & (TT - 1);

    float4 xc = *(const float4*)(x + i);
    float4 xp;
    if (t == 0) { xp = make_float4(0.f, 0.f, 0.f, 0.f); }
    else        { xp = *(const float4*)(x + i - CC); }

    float4 k4 = *(const float4*)(mk + c);
    float4 v4 = *(const float4*)(mv + c);
    float4 r4 = *(const float4*)(mr + c);

    float4 ok, ov, orr;
    ok.x = xc.x*k4.x + xp.x*(1.f-k4.x); ok.y = xc.y*k4.y + xp.y*(1.f-k4.y);
    ok.z = xc.z*k4.z + xp.z*(1.f-k4.z); ok.w = xc.w*k4.w + xp.w*(1.f-k4.w);
    ov.x = xc.x*v4.x + xp.x*(1.f-v4.x); ov.y = xc.y*v4.y + xp.y*(1.f-v4.y);
    ov.z = xc.z*v4.z + xp.z*(1.f-v4.z); ov.w = xc.w*v4.w + xp.w*(1.f-v4.w);
    orr.x = xc.x*r4.x + xp.x*(1.f-r4.x); orr.y = xc.y*r4.y + xp.y*(1.f-r4.y);
    orr.z = xc.z*r4.z + xp.z*(1.f-r4.z); orr.w = xc.w*r4.w + xp.w*(1.f-r4.w);

    *(float4*)(g_xk + i) = ok;
    *(float4*)(g_xv + i) = ov;
    *(float4*)(g_xr + i) = orr;
}

// ---------------- 2) SGEMM: C[M,N] = A[M,K] * B[N,K]^T ----------------
// 128x128 block tile, BK=8, 256 threads, 8x8 per-thread microtile.
template<bool SIGMOID>
__global__ void __launch_bounds__(256) sgemm_abT(
    const float* __restrict__ A,
    const float* __restrict__ B,
    float* __restrict__ C,
    int M, int N, int K)
{
    __shared__ float As[8][128];
    __shared__ float Bs[8][128];

    const int tid = threadIdx.x;
    const int brow = blockIdx.y;       // M tile
    const int bcol = blockIdx.x;       // N tile

    const int loadRow = tid >> 1;            // 0..127
    const int loadCol = (tid & 1) * 4;       // 0 or 4

    const int ty = tid >> 4;                 // 0..15
    const int tx = tid & 15;                 // 0..15

    const float* Aptr = A + (long long)brow * 128 * K;
    const float* Bptr = B + (long long)bcol * 128 * K;

    float acc[8][8];
    #pragma unroll
    for (int i = 0; i < 8; i++)
        #pragma unroll
        for (int j = 0; j < 8; j++) acc[i][j] = 0.f;

    for (int k0 = 0; k0 < K; k0 += 8) {
        float4 a4 = *(const float4*)(Aptr + (long long)loadRow * K + k0 + loadCol);
        float4 b4 = *(const float4*)(Bptr + (long long)loadRow * K + k0 + loadCol);
        As[loadCol+0][loadRow] = a4.x;
        As[loadCol+1][loadRow] = a4.y;
        As[loadCol+2][loadRow] = a4.z;
        As[loadCol+3][loadRow] = a4.w;
        Bs[loadCol+0][loadRow] = b4.x;
        Bs[loadCol+1][loadRow] = b4.y;
        Bs[loadCol+2][loadRow] = b4.z;
        Bs[loadCol+3][loadRow] = b4.w;
        __syncthreads();

        #pragma unroll
        for (int kk = 0; kk < 8; kk++) {
            float ar[8], br[8];
            #pragma unroll
            for (int i = 0; i < 8; i++) ar[i] = As[kk][ty*8 + i];
            #pragma unroll
            for (int j = 0; j < 8; j++) br[j] = Bs[kk][tx*8 + j];
            #pragma unroll
            for (int i = 0; i < 8; i++)
                #pragma unroll
                for (int j = 0; j < 8; j++)
                    acc[i][j] = fmaf(ar[i], br[j], acc[i][j]);
        }
        __syncthreads();
    }

    #pragma unroll
    for (int i = 0; i < 8; i++) {
        long long row = (long long)brow * 128 + ty*8 + i;
        #pragma unroll
        for (int j = 0; j < 8; j++) {
            int col = bcol * 128 + tx*8 + j;
            float val = acc[i][j];
            if (SIGMOID) val = 1.f / (1.f + __expf(-val));
            C[row * N + col] = val;
        }
    }
}

// ---------------- 3) WKV scan + sigmoid gate ----------------
// One thread per (batch, channel). Sequential over T (baseline; chunk-parallel later).
__global__ void __launch_bounds__(256) wkv_kernel(
    const float* __restrict__ time_decay,
    const float* __restrict__ time_first)
{
    int gid = blockIdx.x * blockDim.x + threadIdx.x;   // 0 .. BB*CC-1
    if (gid >= BB * CC) return;
    int b = gid >> 10;          // / CC
    int c = gid & (CC - 1);

    float w = -__expf(time_decay[c]);
    float u = time_first[c];

    const float* kp  = g_k    + (long long)b * TT * CC + c;
    const float* vp  = g_v    + (long long)b * TT * CC + c;
    const float* srp = g_sr   + (long long)b * TT * CC + c;
    float*       op  = g_rwkv + (long long)b * TT * CC + c;

    float aa = 0.f, bb = 0.f, pp = -1e38f;

    for (int t = 0; t < TT; t++) {
        float kt = kp[(long long)t * CC];
        float vt = vp[(long long)t * CC];
        float st = srp[(long long)t * CC];

        float ww = u + kt;
        float p  = fmaxf(pp, ww);
        float e1 = __expf(pp - p);
        float e2 = __expf(ww - p);
        float y  = fmaf(e1, aa, e2 * vt) / fmaf(e1, bb, e2);
        op[(long long)t * CC] = st * y;

        float ww2 = pp + w;
        float p2  = fmaxf(ww2, kt);
        e1 = __expf(ww2 - p2);
        e2 = __expf(kt - p2);
        aa = fmaf(e1, aa, e2 * vt);
        bb = fmaf(e1, bb, e2);
        pp = p2;
    }
}

// ---------------- launch ----------------
extern "C" void kernel_launch(void* const* d_in, const int* in_sizes, int n_in,
                              void* d_out, int out_size)
{
    const float* x  = (const float*)d_in[0];
    const float* td = (const float*)d_in[1];
    const float* tf = (const float*)d_in[2];
    const float* mk = (const float*)d_in[3];
    const float* mv = (const float*)d_in[4];
    const float* mr = (const float*)d_in[5];
    const float* Wk = (const float*)d_in[6];
    const float* Wv = (const float*)d_in[7];
    const float* Wr = (const float*)d_in[8];
    const float* Wo = (const float*)d_in[9];
    float* out = (float*)d_out;

    // resolve scratch addresses (host API, capture-safe, no allocation)
    float *p_xk, *p_xv, *p_xr, *p_k, *p_v, *p_sr, *p_rwkv;
    cudaGetSymbolAddress((void**)&p_xk,   g_xk);
    cudaGetSymbolAddress((void**)&p_xv,   g_xv);
    cudaGetSymbolAddress((void**)&p_xr,   g_xr);
    cudaGetSymbolAddress((void**)&p_k,    g_k);
    cudaGetSymbolAddress((void**)&p_v,    g_v);
    cudaGetSymbolAddress((void**)&p_sr,   g_sr);
    cudaGetSymbolAddress((void**)&p_rwkv, g_rwkv);

    // 1) mix
    {
        long long n4 = (long long)MT * CC / 4;
        int blocks = (int)((n4 + 255) / 256);
        mix_kernel<<<blocks, 256>>>(x, mk, mv, mr);
    }

    // 2) three projection GEMMs (sigmoid fused into r)
    dim3 gemm_grid(CC / 128, MT / 128);     // (8, 128)
    sgemm_abT<false><<<gemm_grid, 256>>>(p_xk, Wk, p_k,  MT, CC, CC);
    sgemm_abT<false><<<gemm_grid, 256>>>(p_xv, Wv, p_v,  MT, CC, CC);
    sgemm_abT<true ><<<gemm_grid, 256>>>(p_xr, Wr, p_sr, MT, CC, CC);

    // 3) WKV scan + gate
    wkv_kernel<<<(BB * CC + 255) / 256, 256>>>(td, tf);

    // 4) output GEMM
    sgemm_abT<false><<<gemm_grid, 256>>>(p_rwkv, Wo, out, MT, CC, CC);
}

// round 3
// speedup vs baseline: 3.8603x; 3.8603x over previous
#include <cuda_runtime.h>
#include <cuda_bf16.h>
#include <cstdint>

#define BB 4
#define TT 4096
#define CC 1024
#define MT (BB*TT)          // 16384 rows
#define CHUNK 64
#define NCH (TT/CHUNK)      // 64 chunks

// ---------------- scratch (no cudaMalloc allowed) ----------------
__device__ float g_xk[MT*CC];
__device__ float g_xv[MT*CC];
__device__ float g_xr[MT*CC];
__device__ float g_k [MT*CC];
__device__ float g_v [MT*CC];
__device__ float g_sr[MT*CC];
__device__ float g_rwkv[MT*CC];
__device__ float g_cA[BB*NCH*CC];
__device__ float g_cB[BB*NCH*CC];

// ================= fast math (FMA-pipe, avoid MUFU) =================
__device__ __forceinline__ float fast_exp(float x) {
    float t = fmaf(x, 1.4426950408889634f, 12582912.0f);
    float n = t - 12582912.0f;                       // rint(x*log2e)
    float r = fmaf(x, 1.4426950408889634f, -n);      // in [-0.5, 0.5]
    float p = 1.3333558146e-3f;
    p = fmaf(p, r, 9.6181291076e-3f);
    p = fmaf(p, r, 5.5504108664e-2f);
    p = fmaf(p, r, 2.4022650696e-1f);
    p = fmaf(p, r, 6.9314718056e-1f);
    p = fmaf(p, r, 1.0f);
    int ei = (int)n;
    if (ei < -126) return 0.0f;
    if (ei > 127) ei = 127;
    return p * __int_as_float((ei + 127) << 23);
}

__device__ __forceinline__ float fast_rcp(float d) {
    float x = __int_as_float(0x7EF311C3 - __float_as_int(d));
    x = x * fmaf(-d, x, 2.0f);
    x = x * fmaf(-d, x, 2.0f);
    x = x * fmaf(-d, x, 2.0f);
    return x;
}

__device__ __forceinline__ float fast_sigmoid(float x) {
    return fast_rcp(1.0f + fast_exp(-x));
}

// ================= mma helpers (arch-generic PTX only) =================
__device__ __forceinline__ uint32_t smem_u32(const void* p) {
    uint32_t a;
    asm("{ .reg .u64 t; cvta.to.shared.u64 t, %1; cvt.u32.u64 %0, t; }" : "=r"(a) : "l"(p));
    return a;
}

__device__ __forceinline__ void ldmx4(uint32_t r[4], uint32_t addr) {
    asm volatile("ldmatrix.sync.aligned.m8n8.x4.shared.b16 {%0,%1,%2,%3}, [%4];"
        : "=r"(r[0]), "=r"(r[1]), "=r"(r[2]), "=r"(r[3]) : "r"(addr));
}

__device__ __forceinline__ void mma_bf16(float c[4], const uint32_t a[4],
                                         uint32_t b0, uint32_t b1) {
    asm volatile(
        "mma.sync.aligned.m16n8k16.row.col.f32.bf16.bf16.f32 "
        "{%0,%1,%2,%3}, {%4,%5,%6,%7}, {%8,%9}, {%0,%1,%2,%3};"
        : "+f"(c[0]), "+f"(c[1]), "+f"(c[2]), "+f"(c[3])
        : "r"(a[0]), "r"(a[1]), "r"(a[2]), "r"(a[3]), "r"(b0), "r"(b1));
}

// split fp32 pair into packed bf16 hi / lo
__device__ __forceinline__ void split2(float x, float y, uint32_t& hi, uint32_t& lo) {
    __nv_bfloat16 hx = __float2bfloat16_rn(x);
    __nv_bfloat16 hy = __float2bfloat16_rn(y);
    float rx = x - __bfloat162float(hx);
    float ry = y - __bfloat162float(hy);
    __nv_bfloat16 lx = __float2bfloat16_rn(rx);
    __nv_bfloat16 ly = __float2bfloat16_rn(ry);
    hi = (uint32_t)__bfloat16_as_ushort(hx) | ((uint32_t)__bfloat16_as_ushort(hy) << 16);
    lo = (uint32_t)__bfloat16_as_ushort(lx) | ((uint32_t)__bfloat16_as_ushort(ly) << 16);
}

// ---------------- 1) token-shift mix ----------------
__global__ void __launch_bounds__(256) mix_kernel(
    const float* __restrict__ x,
    const float* __restrict__ mk,
    const float* __restrict__ mv,
    const float* __restrict__ mr)
{
    long long idx = (long long)blockIdx.x * blockDim.x + threadIdx.x;
    long long i = idx * 4;
    if (i >= (long long)MT * CC) return;
    int c = (int)(i & (CC - 1));
    int m = (int)(i >> 10);
    int t = m & (TT - 1);

    float4 xc = *(const float4*)(x + i);
    float4 xp;
    if (t == 0) xp = make_float4(0.f, 0.f, 0.f, 0.f);
    else        xp = *(const float4*)(x + i - CC);

    float4 k4 = *(const float4*)(mk + c);
    float4 v4 = *(const float4*)(mv + c);
    float4 r4 = *(const float4*)(mr + c);

    float4 ok, ov, orr;
    ok.x = xc.x*k4.x + xp.x*(1.f-k4.x); ok.y = xc.y*k4.y + xp.y*(1.f-k4.y);
    ok.z = xc.z*k4.z + xp.z*(1.f-k4.z); ok.w = xc.w*k4.w + xp.w*(1.f-k4.w);
    ov.x = xc.x*v4.x + xp.x*(1.f-v4.x); ov.y = xc.y*v4.y + xp.y*(1.f-v4.y);
    ov.z = xc.z*v4.z + xp.z*(1.f-v4.z); ov.w = xc.w*v4.w + xp.w*(1.f-v4.w);
    orr.x = xc.x*r4.x + xp.x*(1.f-r4.x); orr.y = xc.y*r4.y + xp.y*(1.f-r4.y);
    orr.z = xc.z*r4.z + xp.z*(1.f-r4.z); orr.w = xc.w*r4.w + xp.w*(1.f-r4.w);

    *(float4*)(g_xk + i) = ok;
    *(float4*)(g_xv + i) = ov;
    *(float4*)(g_xr + i) = orr;
}

// ---------------- 2) mma.sync bf16x3 GEMM: C[M,N] = A[M,K] * B[N,K]^T ----------------
// 128x128 tile, BK=32. SMEM per stage: Ah, Al, Bh, Bl each 128 rows x 80B = 40960B.
#define SROW 80
#define TILE_B (128*SROW)          // 10240
#define STAGE_B (4*TILE_B)         // 40960
#define GEMM_SMEM (2*STAGE_B)      // 81920

template<bool SIGMOID>
__global__ void __launch_bounds__(256, 1) gemm_bf16x3(
    const float* __restrict__ A,
    const float* __restrict__ B,
    float* __restrict__ C)
{
    extern __shared__ char smem[];
    const uint32_t sbase0 = smem_u32(smem);

    const int tid = threadIdx.x;
    const int lid = tid & 31;
    const int wid = tid >> 5;
    const int warp_m = wid & 1;        // 2 x 64 rows
    const int warp_n = wid >> 1;       // 4 x 32 cols
    const int brow = blockIdx.y;
    const int bcol = blockIdx.x;

    // ---- global load pointers: 4 float4 each for A and B per thread ----
    const float* apt[4];
    const float* bpt[4];
    uint32_t soff[4];
    {
        const float* Ag = A + (size_t)brow * 128 * CC;
        const float* Bg = B + (size_t)bcol * 128 * CC;
        #pragma unroll
        for (int i = 0; i < 4; i++) {
            int vid = tid + i * 256;
            int row = vid >> 3;            // 0..127
            int c4  = vid & 7;             // float4 index in row of 32
            apt[i] = Ag + (size_t)row * CC + c4 * 4;
            bpt[i] = Bg + (size_t)row * CC + c4 * 4;
            soff[i] = (uint32_t)(row * SROW + c4 * 8);
        }
    }

    // ---- ldmatrix per-lane address components ----
    // A x4 (16x16): m = lane/8: rows {0-7,8-15,0-7,8-15}, col {0,0,16,16}
    const uint32_t a_off = (uint32_t)((warp_m * 64 + ((lid >> 3) & 1) * 8 + (lid & 7)) * SROW
                                      + ((lid >> 4) & 1) * 16);
    // B x4 (two n8 tiles): rows n = (lane/16)*8 + lane%8, col = ((lane/8)&1)*16
    const uint32_t b_off = (uint32_t)((warp_n * 32 + (lid >> 4) * 8 + (lid & 7)) * SROW
                                      + ((lid >> 3) & 1) * 16);

    float acc[4][4][4];
    #pragma unroll
    for (int mt = 0; mt < 4; mt++)
        #pragma unroll
        for (int nt = 0; nt < 4; nt++)
            #pragma unroll
            for (int e = 0; e < 4; e++) acc[mt][nt][e] = 0.f;

    float4 pa[4], pb[4];
    #pragma unroll
    for (int i = 0; i < 4; i++) { pa[i] = *(const float4*)apt[i]; pb[i] = *(const float4*)bpt[i]; }

    // convert + store stage 0
    #pragma unroll
    for (int i = 0; i < 4; i++) {
        uint32_t h0, l0, h1, l1;
        split2(pa[i].x, pa[i].y, h0, l0);
        split2(pa[i].z, pa[i].w, h1, l1);
        *(uint2*)(smem + soff[i])          = make_uint2(h0, h1);
        *(uint2*)(smem + soff[i] + TILE_B) = make_uint2(l0, l1);
        split2(pb[i].x, pb[i].y, h0, l0);
        split2(pb[i].z, pb[i].w, h1, l1);
        *(uint2*)(smem + soff[i] + 2*TILE_B) = make_uint2(h0, h1);
        *(uint2*)(smem + soff[i] + 3*TILE_B) = make_uint2(l0, l1);
    }
    __syncthreads();

    const int NK = CC / 32;   // 32
    for (int kc = 0; kc < NK; kc++) {
        const int cur = kc & 1;
        const uint32_t sb = sbase0 + cur * STAGE_B;

        // prefetch next fp32 tiles
        if (kc + 1 < NK) {
            #pragma unroll
            for (int i = 0; i < 4; i++) {
                apt[i] += 32; bpt[i] += 32;
                pa[i] = *(const float4*)apt[i];
                pb[i] = *(const float4*)bpt[i];
            }
        }

        // ---- mma over current stage: 2 x k16 ----
        #pragma unroll
        for (int ks = 0; ks < 2; ks++) {
            uint32_t bh[2][4], bl[2][4], ar[4][4];
            #pragma unroll
            for (int p = 0; p < 2; p++) {
                uint32_t addr = sb + 2*TILE_B + b_off + p * (16 * SROW) + ks * 32;
                ldmx4(bh[p], addr);
                ldmx4(bl[p], addr + TILE_B);
            }
            #pragma unroll
            for (int mt = 0; mt < 4; mt++)
                ldmx4(ar[mt], sb + a_off + mt * (16 * SROW) + ks * 32);

            #pragma unroll
            for (int mt = 0; mt < 4; mt++)
                #pragma unroll
                for (int nt = 0; nt < 4; nt++) {
                    int p = nt >> 1, q = (nt & 1) * 2;
                    mma_bf16(acc[mt][nt], ar[mt], bh[p][q], bh[p][q+1]);   // Ah*Bh
                    mma_bf16(acc[mt][nt], ar[mt], bl[p][q], bl[p][q+1]);   // Ah*Bl
                }
            #pragma unroll
            for (int mt = 0; mt < 4; mt++)
                ldmx4(ar[mt], sb + TILE_B + a_off + mt * (16 * SROW) + ks * 32);
            #pragma unroll
            for (int mt = 0; mt < 4; mt++)
                #pragma unroll
                for (int nt = 0; nt < 4; nt++) {
                    int p = nt >> 1, q = (nt & 1) * 2;
                    mma_bf16(acc[mt][nt], ar[mt], bh[p][q], bh[p][q+1]);   // Al*Bh
                }
        }

        // store next stage
        if (kc + 1 < NK) {
            char* sn = smem + (cur ^ 1) * STAGE_B;
            #pragma unroll
            for (int i = 0; i < 4; i++) {
                uint32_t h0, l0, h1, l1;
                split2(pa[i].x, pa[i].y, h0, l0);
                split2(pa[i].z, pa[i].w, h1, l1);
                *(uint2*)(sn + soff[i])          = make_uint2(h0, h1);
                *(uint2*)(sn + soff[i] + TILE_B) = make_uint2(l0, l1);
                split2(pb[i].x, pb[i].y, h0, l0);
                split2(pb[i].z, pb[i].w, h1, l1);
                *(uint2*)(sn + soff[i] + 2*TILE_B) = make_uint2(h0, h1);
                *(uint2*)(sn + soff[i] + 3*TILE_B) = make_uint2(l0, l1);
            }
        }
        __syncthreads();
    }

    // ---- epilogue ----
    const int r0 = (lid >> 2);
    const int c0 = (lid & 3) * 2;
    #pragma unroll
    for (int mt = 0; mt < 4; mt++) {
        size_t grow = (size_t)brow * 128 + warp_m * 64 + mt * 16 + r0;
        #pragma unroll
        for (int nt = 0; nt < 4; nt++) {
            int gcol = bcol * 128 + warp_n * 32 + nt * 8 + c0;
            float d0 = acc[mt][nt][0], d1 = acc[mt][nt][1];
            float d2 = acc[mt][nt][2], d3 = acc[mt][nt][3];
            if (SIGMOID) {
                d0 = fast_sigmoid(d0); d1 = fast_sigmoid(d1);
                d2 = fast_sigmoid(d2); d3 = fast_sigmoid(d3);
            }
            *(float2*)(C + grow * CC + gcol)       = make_float2(d0, d1);
            *(float2*)(C + (grow + 8) * CC + gcol) = make_float2(d2, d3);
        }
    }
}

// ---------------- 3) WKV: chunk-parallel 3-pass scan ----------------
__global__ void __launch_bounds__(256) wkv_pass1(const float* __restrict__ td)
{
    int gid = blockIdx.x * 256 + threadIdx.x;
    int c = gid & (CC - 1);
    int bj = gid >> 10;
    int b = bj >> 6;
    int j = bj & (NCH - 1);

    float w = -fast_exp(td[c]);
    float ew = fast_exp(w);

    size_t base = ((size_t)b * TT + (size_t)j * CHUNK) * CC + c;
    const float* kp = g_k + base;
    const float* vp = g_v + base;

    float A = 0.f, Bv = 0.f;
    for (int s = 0; s < CHUNK; s++) {
        float kt = kp[(size_t)s * CC];
        float vt = vp[(size_t)s * CC];
        float ek = fast_exp(kt);
        A = fmaf(A, ew, ek * vt);
        Bv = fmaf(Bv, ew, ek);
    }
    g_cA[gid] = A;
    g_cB[gid] = Bv;
}

__global__ void __launch_bounds__(256) wkv_combine(const float* __restrict__ td)
{
    int gid = blockIdx.x * 256 + threadIdx.x;
    if (gid >= BB * CC) return;
    int c = gid & (CC - 1);
    int b = gid >> 10;

    float w = -fast_exp(td[c]);
    float ewL = fast_exp(w * (float)CHUNK);

    float A = 0.f, Bv = 0.f;
    for (int j = 0; j < NCH; j++) {
        size_t idx = ((size_t)b * NCH + j) * CC + c;
        float ca = g_cA[idx], cb = g_cB[idx];
        g_cA[idx] = A;
        g_cB[idx] = Bv;
        A = fmaf(A, ewL, ca);
        Bv = fmaf(Bv, ewL, cb);
    }
}

__global__ void __launch_bounds__(256) wkv_pass2(const float* __restrict__ td,
                                                 const float* __restrict__ tf)
{
    int gid = blockIdx.x * 256 + threadIdx.x;
    int c = gid & (CC - 1);
    int bj = gid >> 10;
    int b = bj >> 6;
    int j = bj & (NCH - 1);

    float w = -fast_exp(td[c]);
    float ew = fast_exp(w);
    float eu = fast_exp(tf[c]);

    float A = g_cA[gid];
    float Bv = g_cB[gid];

    size_t base = ((size_t)b * TT + (size_t)j * CHUNK) * CC + c;
    const float* kp = g_k + base;
    const float* vp = g_v + base;
    const float* sp = g_sr + base;
    float* op = g_rwkv + base;

    for (int s = 0; s < CHUNK; s++) {
        float kt = kp[(size_t)s * CC];
        float vt = vp[(size_t)s * CC];
        float st = sp[(size_t)s * CC];
        float ek = fast_exp(kt);
        float euk = eu * ek;
        float y = fmaf(euk, vt, A) * fast_rcp(Bv + euk);
        op[(size_t)s * CC] = st * y;
        A = fmaf(A, ew, ek * vt);
        Bv = fmaf(Bv, ew, ek);
    }
}

// ---------------- launch ----------------
extern "C" void kernel_launch(void* const* d_in, const int* in_sizes, int n_in,
                              void* d_out, int out_size)
{
    const float* x  = (const float*)d_in[0];
    const float* td = (const float*)d_in[1];
    const float* tf = (const float*)d_in[2];
    const float* mk = (const float*)d_in[3];
    const float* mv = (const float*)d_in[4];
    const float* mr = (const float*)d_in[5];
    const float* Wk = (const float*)d_in[6];
    const float* Wv = (const float*)d_in[7];
    const float* Wr = (const float*)d_in[8];
    const float* Wo = (const float*)d_in[9];
    float* out = (float*)d_out;

    float *p_xk, *p_xv, *p_xr, *p_k, *p_v, *p_sr, *p_rwkv;
    cudaGetSymbolAddress((void**)&p_xk,   g_xk);
    cudaGetSymbolAddress((void**)&p_xv,   g_xv);
    cudaGetSymbolAddress((void**)&p_xr,   g_xr);
    cudaGetSymbolAddress((void**)&p_k,    g_k);
    cudaGetSymbolAddress((void**)&p_v,    g_v);
    cudaGetSymbolAddress((void**)&p_sr,   g_sr);
    cudaGetSymbolAddress((void**)&p_rwkv, g_rwkv);

    cudaFuncSetAttribute(gemm_bf16x3<false>, cudaFuncAttributeMaxDynamicSharedMemorySize, GEMM_SMEM);
    cudaFuncSetAttribute(gemm_bf16x3<true>,  cudaFuncAttributeMaxDynamicSharedMemorySize, GEMM_SMEM);

    // 1) mix
    {
        long long n4 = (long long)MT * CC / 4;
        int blocks = (int)((n4 + 255) / 256);
        mix_kernel<<<blocks, 256>>>(x, mk, mv, mr);
    }

    // 2) projection GEMMs (sigmoid fused into r)
    dim3 gg(CC / 128, MT / 128);   // (8, 128)
    gemm_bf16x3<false><<<gg, 256, GEMM_SMEM>>>(p_xk, Wk, p_k);
    gemm_bf16x3<false><<<gg, 256, GEMM_SMEM>>>(p_xv, Wv, p_v);
    gemm_bf16x3<true ><<<gg, 256, GEMM_SMEM>>>(p_xr, Wr, p_sr);

    // 3) WKV chunk-parallel scan
    {
        int n1 = BB * NCH * CC;                    // 262144
        wkv_pass1<<<n1 / 256, 256>>>(td);
        wkv_combine<<<(BB * CC + 255) / 256, 256>>>(td);
        wkv_pass2<<<n1 / 256, 256>>>(td, tf);
    }

    // 4) output GEMM
    gemm_bf16x3<false><<<gg, 256, GEMM_SMEM>>>(p_rwkv, Wo, out);
}

// round 4
// speedup vs baseline: 5.4693x; 1.4168x over previous
#include <cuda_runtime.h>
#include <cuda_bf16.h>
#include <cstdint>

#define BB 4
#define TT 4096
#define CC 1024
#define MT (BB*TT)          // 16384 rows
#define CHUNK 64
#define NCH (TT/CHUNK)      // 64 chunks

// ---------------- scratch (no cudaMalloc allowed) ----------------
__device__ __align__(128) __nv_bfloat16 g_xk_h[MT*CC];
__device__ __align__(128) __nv_bfloat16 g_xk_l[MT*CC];
__device__ __align__(128) __nv_bfloat16 g_xv_h[MT*CC];
__device__ __align__(128) __nv_bfloat16 g_xv_l[MT*CC];
__device__ __align__(128) __nv_bfloat16 g_xr_h[MT*CC];
__device__ __align__(128) __nv_bfloat16 g_xr_l[MT*CC];
__device__ __align__(128) __nv_bfloat16 g_rw_h[MT*CC];
__device__ __align__(128) __nv_bfloat16 g_rw_l[MT*CC];
__device__ __align__(128) __nv_bfloat16 g_w_h[4*CC*CC];
__device__ __align__(128) __nv_bfloat16 g_w_l[4*CC*CC];
__device__ float g_k [MT*CC];
__device__ float g_v [MT*CC];
__device__ float g_sr[MT*CC];
__device__ float g_cA[BB*NCH*CC];
__device__ float g_cB[BB*NCH*CC];

// ================= fast math (FMA-pipe, avoid MUFU) =================
__device__ __forceinline__ float fast_exp(float x) {
    float t = fmaf(x, 1.4426950408889634f, 12582912.0f);
    float n = t - 12582912.0f;
    float r = fmaf(x, 1.4426950408889634f, -n);
    float p = 1.3333558146e-3f;
    p = fmaf(p, r, 9.6181291076e-3f);
    p = fmaf(p, r, 5.5504108664e-2f);
    p = fmaf(p, r, 2.4022650696e-1f);
    p = fmaf(p, r, 6.9314718056e-1f);
    p = fmaf(p, r, 1.0f);
    int ei = (int)n;
    if (ei < -126) return 0.0f;
    if (ei > 127) ei = 127;
    return p * __int_as_float((ei + 127) << 23);
}

__device__ __forceinline__ float fast_rcp(float d) {
    float x = __int_as_float(0x7EF311C3 - __float_as_int(d));
    x = x * fmaf(-d, x, 2.0f);
    x = x * fmaf(-d, x, 2.0f);
    x = x * fmaf(-d, x, 2.0f);
    return x;
}

__device__ __forceinline__ float fast_sigmoid(float x) {
    return fast_rcp(1.0f + fast_exp(-x));
}

// ================= PTX helpers (arch-generic only) =================
__device__ __forceinline__ uint32_t smem_u32(const void* p) {
    uint32_t a;
    asm("{ .reg .u64 t; cvta.to.shared.u64 t, %1; cvt.u32.u64 %0, t; }" : "=r"(a) : "l"(p));
    return a;
}

__device__ __forceinline__ void ldmx4(uint32_t r[4], uint32_t addr) {
    asm volatile("ldmatrix.sync.aligned.m8n8.x4.shared.b16 {%0,%1,%2,%3}, [%4];"
        : "=r"(r[0]), "=r"(r[1]), "=r"(r[2]), "=r"(r[3]) : "r"(addr));
}

__device__ __forceinline__ void mma_bf16(float c[4], const uint32_t a[4],
                                         uint32_t b0, uint32_t b1) {
    asm volatile(
        "mma.sync.aligned.m16n8k16.row.col.f32.bf16.bf16.f32 "
        "{%0,%1,%2,%3}, {%4,%5,%6,%7}, {%8,%9}, {%0,%1,%2,%3};"
        : "+f"(c[0]), "+f"(c[1]), "+f"(c[2]), "+f"(c[3])
        : "r"(a[0]), "r"(a[1]), "r"(a[2]), "r"(a[3]), "r"(b0), "r"(b1));
}

__device__ __forceinline__ void cpa16(uint32_t dst, const void* src) {
    asm volatile("cp.async.cg.shared.global [%0], [%1], 16;" :: "r"(dst), "l"(src));
}
#define CP_COMMIT() asm volatile("cp.async.commit_group;" ::: "memory")
#define CP_WAIT1()  asm volatile("cp.async.wait_group 1;" ::: "memory")

// split fp32 pair into packed bf16 hi / lo
__device__ __forceinline__ void split2(float x, float y, uint32_t& hi, uint32_t& lo) {
    __nv_bfloat16 hx = __float2bfloat16_rn(x);
    __nv_bfloat16 hy = __float2bfloat16_rn(y);
    float rx = x - __bfloat162float(hx);
    float ry = y - __bfloat162float(hy);
    __nv_bfloat16 lx = __float2bfloat16_rn(rx);
    __nv_bfloat16 ly = __float2bfloat16_rn(ry);
    hi = (uint32_t)__bfloat16_as_ushort(hx) | ((uint32_t)__bfloat16_as_ushort(hy) << 16);
    lo = (uint32_t)__bfloat16_as_ushort(lx) | ((uint32_t)__bfloat16_as_ushort(ly) << 16);
}

__device__ __forceinline__ void split4_store(float4 o, __nv_bfloat16* ph, __nv_bfloat16* pl, long long i) {
    uint32_t h0, l0, h1, l1;
    split2(o.x, o.y, h0, l0);
    split2(o.z, o.w, h1, l1);
    *(uint2*)(ph + i) = make_uint2(h0, h1);
    *(uint2*)(pl + i) = make_uint2(l0, l1);
}

// ---------------- 0) weight convert (fp32 -> bf16 hi/lo) ----------------
__global__ void __launch_bounds__(256) convert_w(
    const float* __restrict__ Wk, const float* __restrict__ Wv,
    const float* __restrict__ Wr, const float* __restrict__ Wo)
{
    long long gid = (long long)blockIdx.x * 256 + threadIdx.x;
    long long i = gid * 4;                      // over 4*CC*CC
    if (i >= 4LL*CC*CC) return;
    int w = (int)(i >> 20);                     // / (CC*CC)
    long long off = i & (CC*CC - 1);
    const float* src = (w == 0) ? Wk : (w == 1) ? Wv : (w == 2) ? Wr : Wo;
    float4 v = *(const float4*)(src + off);
    split4_store(v, g_w_h + i, g_w_l + i, 0);
}

// ---------------- 1) token-shift mix -> bf16 hi/lo ----------------
__global__ void __launch_bounds__(256) mix_kernel(
    const float* __restrict__ x,
    const float* __restrict__ mk,
    const float* __restrict__ mv,
    const float* __restrict__ mr)
{
    long long idx = (long long)blockIdx.x * blockDim.x + threadIdx.x;
    long long i = idx * 4;
    if (i >= (long long)MT * CC) return;
    int c = (int)(i & (CC - 1));
    int m = (int)(i >> 10);
    int t = m & (TT - 1);

    float4 xc = *(const float4*)(x + i);
    float4 xp;
    if (t == 0) xp = make_float4(0.f, 0.f, 0.f, 0.f);
    else        xp = *(const float4*)(x + i - CC);

    float4 k4 = *(const float4*)(mk + c);
    float4 v4 = *(const float4*)(mv + c);
    float4 r4 = *(const float4*)(mr + c);

    float4 o;
    o.x = xc.x*k4.x + xp.x*(1.f-k4.x); o.y = xc.y*k4.y + xp.y*(1.f-k4.y);
    o.z = xc.z*k4.z + xp.z*(1.f-k4.z); o.w = xc.w*k4.w + xp.w*(1.f-k4.w);
    split4_store(o, g_xk_h + i, g_xk_l + i, 0);
    o.x = xc.x*v4.x + xp.x*(1.f-v4.x); o.y = xc.y*v4.y + xp.y*(1.f-v4.y);
    o.z = xc.z*v4.z + xp.z*(1.f-v4.z); o.w = xc.w*v4.w + xp.w*(1.f-v4.w);
    split4_store(o, g_xv_h + i, g_xv_l + i, 0);
    o.x = xc.x*r4.x + xp.x*(1.f-r4.x); o.y = xc.y*r4.y + xp.y*(1.f-r4.y);
    o.z = xc.z*r4.z + xp.z*(1.f-r4.z); o.w = xc.w*r4.w + xp.w*(1.f-r4.w);
    split4_store(o, g_xr_h + i, g_xr_l + i, 0);
}

// ---------------- 2) cp.async pipelined bf16x3 GEMM ----------------
// C[M,N] = A[M,K] * B[N,K]^T ; tile 128x128, BK=64, 3 stages.
// Stage layout: [A_hi 16K][A_lo 16K][B_hi 16K][B_lo 16K] = 64KB, SW128 swizzle.
#define STG_B  65536
#define STAGES 3
#define GEMM_SMEM (STAGES*STG_B)   // 196608

template<bool SIGMOID>
__global__ void __launch_bounds__(256, 1) gemm_bf16x3(
    const __nv_bfloat16* __restrict__ Ah, const __nv_bfloat16* __restrict__ Al,
    const __nv_bfloat16* __restrict__ Bh, const __nv_bfloat16* __restrict__ Bl,
    float* __restrict__ C)
{
    extern __shared__ char smem[];
    const uint32_t sb0 = smem_u32(smem);

    const int tid = threadIdx.x;
    const int lid = tid & 31;
    const int wid = tid >> 5;
    const int warp_m = wid & 1;
    const int warp_n = wid >> 1;
    const int brow = blockIdx.y;
    const int bcol = blockIdx.x;

    // ---- cp.async assignment: 4 chunks of 16B per thread per 16KB tile ----
    const __nv_bfloat16 *pAh[4], *pAl[4], *pBh[4], *pBl[4];
    uint32_t sdst[4];
    #pragma unroll
    for (int j = 0; j < 4; j++) {
        int cid = tid + j * 256;         // 0..1023
        int row = cid >> 3;              // 0..127
        int ch  = cid & 7;               // 16B chunk in 128B row
        size_t aoff = ((size_t)(brow * 128 + row)) * CC + ch * 8;
        size_t boff = ((size_t)(bcol * 128 + row)) * CC + ch * 8;
        pAh[j] = Ah + aoff;  pAl[j] = Al + aoff;
        pBh[j] = Bh + boff;  pBl[j] = Bl + boff;
        sdst[j] = (uint32_t)(row * 128 + ((ch ^ (row & 7)) << 4));
    }

    // ---- ldmatrix per-lane components ----
    const int a_row  = warp_m * 64 + ((lid >> 3) & 1) * 8 + (lid & 7);
    const int a_half = (lid >> 4) & 1;
    const uint32_t a_x = (uint32_t)(a_row & 7);
    const int b_row  = warp_n * 32 + (lid >> 4) * 8 + (lid & 7);
    const int b_half = (lid >> 3) & 1;
    const uint32_t b_x = (uint32_t)(b_row & 7);

    float acc[4][4][4];
    #pragma unroll
    for (int mt = 0; mt < 4; mt++)
        #pragma unroll
        for (int nt = 0; nt < 4; nt++)
            #pragma unroll
            for (int e = 0; e < 4; e++) acc[mt][nt][e] = 0.f;

    const int NK = CC / 64;   // 16

    // load one stage (pointers advance by 64 elems after each call)
    #define LOAD_STAGE(S) do {                                          \
        uint32_t base = sb0 + (S) * STG_B;                              \
        _Pragma("unroll")                                               \
        for (int j = 0; j < 4; j++) {                                   \
            cpa16(base + sdst[j],          pAh[j]);  pAh[j] += 64;      \
            cpa16(base + 16384 + sdst[j],  pAl[j]);  pAl[j] += 64;      \
            cpa16(base + 32768 + sdst[j],  pBh[j]);  pBh[j] += 64;      \
            cpa16(base + 49152 + sdst[j],  pBl[j]);  pBl[j] += 64;      \
        }                                                               \
    } while (0)

    LOAD_STAGE(0); CP_COMMIT();
    LOAD_STAGE(1); CP_COMMIT();

    for (int kc = 0; kc < NK; kc++) {
        CP_WAIT1();
        __syncthreads();
        if (kc + 2 < NK) {
            int s = (kc + 2) % STAGES;
            LOAD_STAGE(s);
        }
        CP_COMMIT();

        const uint32_t sA = sb0 + (kc % STAGES) * STG_B;
        const uint32_t sB = sA + 32768;

        #pragma unroll
        for (int ks = 0; ks < 4; ks++) {
            uint32_t bh[2][4], bl[2][4], ah[4][4], al[4][4];
            const uint32_t ac = ((uint32_t)(ks * 2 + a_half) ^ a_x) << 4;
            const uint32_t bc = ((uint32_t)(ks * 2 + b_half) ^ b_x) << 4;
            #pragma unroll
            for (int p = 0; p < 2; p++) {
                uint32_t addr = sB + (uint32_t)(b_row + p * 16) * 128 + bc;
                ldmx4(bh[p], addr);
                ldmx4(bl[p], addr + 16384);
            }
            #pragma unroll
            for (int mt = 0; mt < 4; mt++) {
                uint32_t addr = sA + (uint32_t)(a_row + mt * 16) * 128 + ac;
                ldmx4(ah[mt], addr);
                ldmx4(al[mt], addr + 16384);
            }
            #pragma unroll
            for (int mt = 0; mt < 4; mt++)
                #pragma unroll
                for (int nt = 0; nt < 4; nt++) {
                    int p = nt >> 1, q = (nt & 1) * 2;
                    mma_bf16(acc[mt][nt], ah[mt], bh[p][q], bh[p][q+1]);  // Ah*Bh
                    mma_bf16(acc[mt][nt], ah[mt], bl[p][q], bl[p][q+1]);  // Ah*Bl
                    mma_bf16(acc[mt][nt], al[mt], bh[p][q], bh[p][q+1]);  // Al*Bh
                }
        }
    }
    #undef LOAD_STAGE

    // ---- epilogue ----
    const int r0 = (lid >> 2);
    const int c0 = (lid & 3) * 2;
    #pragma unroll
    for (int mt = 0; mt < 4; mt++) {
        size_t grow = (size_t)brow * 128 + warp_m * 64 + mt * 16 + r0;
        #pragma unroll
        for (int nt = 0; nt < 4; nt++) {
            int gcol = bcol * 128 + warp_n * 32 + nt * 8 + c0;
            float d0 = acc[mt][nt][0], d1 = acc[mt][nt][1];
            float d2 = acc[mt][nt][2], d3 = acc[mt][nt][3];
            if (SIGMOID) {
                d0 = fast_sigmoid(d0); d1 = fast_sigmoid(d1);
                d2 = fast_sigmoid(d2); d3 = fast_sigmoid(d3);
            }
            *(float2*)(C + grow * CC + gcol)       = make_float2(d0, d1);
            *(float2*)(C + (grow + 8) * CC + gcol) = make_float2(d2, d3);
        }
    }
}

// ---------------- 3) WKV: chunk-parallel 3-pass scan ----------------
__global__ void __launch_bounds__(256) wkv_pass1(const float* __restrict__ td)
{
    int gid = blockIdx.x * 256 + threadIdx.x;
    int c = gid & (CC - 1);
    int bj = gid >> 10;
    int b = bj >> 6;
    int j = bj & (NCH - 1);

    float w = -fast_exp(td[c]);
    float ew = fast_exp(w);

    size_t base = ((size_t)b * TT + (size_t)j * CHUNK) * CC + c;
    const float* kp = g_k + base;
    const float* vp = g_v + base;

    float A = 0.f, Bv = 0.f;
    for (int s = 0; s < CHUNK; s++) {
        float kt = kp[(size_t)s * CC];
        float vt = vp[(size_t)s * CC];
        float ek = fast_exp(kt);
        A = fmaf(A, ew, ek * vt);
        Bv = fmaf(Bv, ew, ek);
    }
    g_cA[gid] = A;
    g_cB[gid] = Bv;
}

__global__ void __launch_bounds__(256) wkv_combine(const float* __restrict__ td)
{
    int gid = blockIdx.x * 256 + threadIdx.x;
    if (gid >= BB * CC) return;
    int c = gid & (CC - 1);
    int b = gid >> 10;

    float w = -fast_exp(td[c]);
    float ewL = fast_exp(w * (float)CHUNK);

    float A = 0.f, Bv = 0.f;
    for (int j = 0; j < NCH; j++) {
        size_t idx = ((size_t)b * NCH + j) * CC + c;
        float ca = g_cA[idx], cb = g_cB[idx];
        g_cA[idx] = A;
        g_cB[idx] = Bv;
        A = fmaf(A, ewL, ca);
        Bv = fmaf(Bv, ewL, cb);
    }
}

__global__ void __launch_bounds__(256) wkv_pass2(const float* __restrict__ td,
                                                 const float* __restrict__ tf)
{
    int gid = blockIdx.x * 256 + threadIdx.x;
    int c = gid & (CC - 1);
    int bj = gid >> 10;
    int b = bj >> 6;
    int j = bj & (NCH - 1);

    float w = -fast_exp(td[c]);
    float ew = fast_exp(w);
    float eu = fast_exp(tf[c]);

    float A = g_cA[gid];
    float Bv = g_cB[gid];

    size_t base = ((size_t)b * TT + (size_t)j * CHUNK) * CC + c;
    const float* kp = g_k + base;
    const float* vp = g_v + base;
    const float* sp = g_sr + base;
    __nv_bfloat16* oh = g_rw_h + base;
    __nv_bfloat16* ol = g_rw_l + base;

    for (int s = 0; s < CHUNK; s++) {
        float kt = kp[(size_t)s * CC];
        float vt = vp[(size_t)s * CC];
        float st = sp[(size_t)s * CC];
        float ek = fast_exp(kt);
        float euk = eu * ek;
        float y = fmaf(euk, vt, A) * fast_rcp(Bv + euk);
        float o = st * y;
        __nv_bfloat16 h = __float2bfloat16_rn(o);
        __nv_bfloat16 l = __float2bfloat16_rn(o - __bfloat162float(h));
        oh[(size_t)s * CC] = h;
        ol[(size_t)s * CC] = l;
        A = fmaf(A, ew, ek * vt);
        Bv = fmaf(Bv, ew, ek);
    }
}

// ---------------- launch ----------------
extern "C" void kernel_launch(void* const* d_in, const int* in_sizes, int n_in,
                              void* d_out, int out_size)
{
    const float* x  = (const float*)d_in[0];
    const float* td = (const float*)d_in[1];
    const float* tf = (const float*)d_in[2];
    const float* mk = (const float*)d_in[3];
    const float* mv = (const float*)d_in[4];
    const float* mr = (const float*)d_in[5];
    const float* Wk = (const float*)d_in[6];
    const float* Wv = (const float*)d_in[7];
    const float* Wr = (const float*)d_in[8];
    const float* Wo = (const float*)d_in[9];
    float* out = (float*)d_out;

    __nv_bfloat16 *xk_h, *xk_l, *xv_h, *xv_l, *xr_h, *xr_l, *rw_h, *rw_l, *w_h, *w_l;
    float *p_k, *p_v, *p_sr;
    cudaGetSymbolAddress((void**)&xk_h, g_xk_h);
    cudaGetSymbolAddress((void**)&xk_l, g_xk_l);
    cudaGetSymbolAddress((void**)&xv_h, g_xv_h);
    cudaGetSymbolAddress((void**)&xv_l, g_xv_l);
    cudaGetSymbolAddress((void**)&xr_h, g_xr_h);
    cudaGetSymbolAddress((void**)&xr_l, g_xr_l);
    cudaGetSymbolAddress((void**)&rw_h, g_rw_h);
    cudaGetSymbolAddress((void**)&rw_l, g_rw_l);
    cudaGetSymbolAddress((void**)&w_h,  g_w_h);
    cudaGetSymbolAddress((void**)&w_l,  g_w_l);
    cudaGetSymbolAddress((void**)&p_k,  g_k);
    cudaGetSymbolAddress((void**)&p_v,  g_v);
    cudaGetSymbolAddress((void**)&p_sr, g_sr);

    cudaFuncSetAttribute(gemm_bf16x3<false>, cudaFuncAttributeMaxDynamicSharedMemorySize, GEMM_SMEM);
    cudaFuncSetAttribute(gemm_bf16x3<true>,  cudaFuncAttributeMaxDynamicSharedMemorySize, GEMM_SMEM);

    // 0) weight convert
    convert_w<<<(4*CC*CC/4 + 255) / 256, 256>>>(Wk, Wv, Wr, Wo);

    // 1) mix -> bf16 hi/lo
    {
        long long n4 = (long long)MT * CC / 4;
        mix_kernel<<<(int)((n4 + 255) / 256), 256>>>(x, mk, mv, mr);
    }

    // 2) projection GEMMs (sigmoid fused into r)
    dim3 gg(CC / 128, MT / 128);   // (8, 128)
    const int WSZ = CC * CC;
    gemm_bf16x3<false><<<gg, 256, GEMM_SMEM>>>(xk_h, xk_l, w_h,         w_l,         p_k);
    gemm_bf16x3<false><<<gg, 256, GEMM_SMEM>>>(xv_h, xv_l, w_h + WSZ,   w_l + WSZ,   p_v);
    gemm_bf16x3<true ><<<gg, 256, GEMM_SMEM>>>(xr_h, xr_l, w_h + 2*WSZ, w_l + 2*WSZ, p_sr);

    // 3) WKV chunk-parallel scan
    {
        int n1 = BB * NCH * CC;
        wkv_pass1<<<n1 / 256, 256>>>(td);
        wkv_combine<<<(BB * CC + 255) / 256, 256>>>(td);
        wkv_pass2<<<n1 / 256, 256>>>(td, tf);
    }

    // 4) output GEMM
    gemm_bf16x3<false><<<gg, 256, GEMM_SMEM>>>(rw_h, rw_l, w_h + 3*WSZ, w_l + 3*WSZ, out);
}

// round 5
// speedup vs baseline: 7.4851x; 1.3686x over previous
#include <cuda_runtime.h>
#include <cuda_fp16.h>
#include <cstdint>

#define BB 4
#define TT 4096
#define CC 1024
#define MT (BB*TT)          // 16384 rows
#define CHUNK 64
#define NCH (TT/CHUNK)      // 64 chunks

// ---------------- scratch (no cudaMalloc allowed) ----------------
__device__ __align__(128) __half g_xk[MT*CC];
__device__ __align__(128) __half g_xv[MT*CC];
__device__ __align__(128) __half g_xr[MT*CC];
__device__ __align__(128) __half g_rw[MT*CC];
__device__ __align__(128) __half g_w_h[4*CC*CC];
__device__ __align__(128) __half g_w_l[4*CC*CC];
__device__ float g_k [MT*CC];
__device__ float g_v [MT*CC];
__device__ float g_sr[MT*CC];
__device__ float g_cA[BB*NCH*CC];
__device__ float g_cB[BB*NCH*CC];

// ================= fast math (FMA-pipe, avoid MUFU) =================
__device__ __forceinline__ float fast_exp(float x) {
    float t = fmaf(x, 1.4426950408889634f, 12582912.0f);
    float n = t - 12582912.0f;
    float r = fmaf(x, 1.4426950408889634f, -n);
    float p = 1.3333558146e-3f;
    p = fmaf(p, r, 9.6181291076e-3f);
    p = fmaf(p, r, 5.5504108664e-2f);
    p = fmaf(p, r, 2.4022650696e-1f);
    p = fmaf(p, r, 6.9314718056e-1f);
    p = fmaf(p, r, 1.0f);
    int ei = (int)n;
    if (ei < -126) return 0.0f;
    if (ei > 127) ei = 127;
    return p * __int_as_float((ei + 127) << 23);
}

__device__ __forceinline__ float fast_rcp(float d) {
    float x = __int_as_float(0x7EF311C3 - __float_as_int(d));
    x = x * fmaf(-d, x, 2.0f);
    x = x * fmaf(-d, x, 2.0f);
    x = x * fmaf(-d, x, 2.0f);
    return x;
}

__device__ __forceinline__ float fast_sigmoid(float x) {
    return fast_rcp(1.0f + fast_exp(-x));
}

// ================= PTX helpers (arch-generic only) =================
__device__ __forceinline__ uint32_t smem_u32(const void* p) {
    uint32_t a;
    asm("{ .reg .u64 t; cvta.to.shared.u64 t, %1; cvt.u32.u64 %0, t; }" : "=r"(a) : "l"(p));
    return a;
}

__device__ __forceinline__ void ldmx4(uint32_t r[4], uint32_t addr) {
    asm volatile("ldmatrix.sync.aligned.m8n8.x4.shared.b16 {%0,%1,%2,%3}, [%4];"
        : "=r"(r[0]), "=r"(r[1]), "=r"(r[2]), "=r"(r[3]) : "r"(addr));
}

__device__ __forceinline__ void mma_fp16(float c[4], const uint32_t a[4],
                                         uint32_t b0, uint32_t b1) {
    asm volatile(
        "mma.sync.aligned.m16n8k16.row.col.f32.f16.f16.f32 "
        "{%0,%1,%2,%3}, {%4,%5,%6,%7}, {%8,%9}, {%0,%1,%2,%3};"
        : "+f"(c[0]), "+f"(c[1]), "+f"(c[2]), "+f"(c[3])
        : "r"(a[0]), "r"(a[1]), "r"(a[2]), "r"(a[3]), "r"(b0), "r"(b1));
}

__device__ __forceinline__ void cpa16(uint32_t dst, const void* src) {
    asm volatile("cp.async.cg.shared.global [%0], [%1], 16;" :: "r"(dst), "l"(src));
}
#define CP_COMMIT() asm volatile("cp.async.commit_group;" ::: "memory")
#define CP_WAIT2()  asm volatile("cp.async.wait_group 2;" ::: "memory")

// pack 4 fp32 -> 4 fp16 (8B)
__device__ __forceinline__ void pack4_store(float4 o, __half* p) {
    __half2 a = __floats2half2_rn(o.x, o.y);
    __half2 b = __floats2half2_rn(o.z, o.w);
    uint2 u;
    u.x = *(uint32_t*)&a;
    u.y = *(uint32_t*)&b;
    *(uint2*)p = u;
}

// ---------------- 0) weight convert (fp32 -> fp16 hi/lo) ----------------
__global__ void __launch_bounds__(256) convert_w(
    const float* __restrict__ Wk, const float* __restrict__ Wv,
    const float* __restrict__ Wr, const float* __restrict__ Wo)
{
    long long gid = (long long)blockIdx.x * 256 + threadIdx.x;
    long long i = gid * 4;
    if (i >= 4LL*CC*CC) return;
    int w = (int)(i >> 20);
    long long off = i & (CC*CC - 1);
    const float* src = (w == 0) ? Wk : (w == 1) ? Wv : (w == 2) ? Wr : Wo;
    float4 v = *(const float4*)(src + off);
    __half hx = __float2half_rn(v.x), hy = __float2half_rn(v.y);
    __half hz = __float2half_rn(v.z), hw = __float2half_rn(v.w);
    float4 lo = make_float4(v.x - __half2float(hx), v.y - __half2float(hy),
                            v.z - __half2float(hz), v.w - __half2float(hw));
    __half2 h01 = __halves2half2(hx, hy);
    __half2 h23 = __halves2half2(hz, hw);
    uint2 hu; hu.x = *(uint32_t*)&h01; hu.y = *(uint32_t*)&h23;
    *(uint2*)(g_w_h + i) = hu;
    pack4_store(lo, g_w_l + i);
}

// ---------------- 1) token-shift mix -> fp16 ----------------
__global__ void __launch_bounds__(256) mix_kernel(
    const float* __restrict__ x,
    const float* __restrict__ mk,
    const float* __restrict__ mv,
    const float* __restrict__ mr)
{
    long long idx = (long long)blockIdx.x * blockDim.x + threadIdx.x;
    long long i = idx * 4;
    if (i >= (long long)MT * CC) return;
    int c = (int)(i & (CC - 1));
    int m = (int)(i >> 10);
    int t = m & (TT - 1);

    float4 xc = *(const float4*)(x + i);
    float4 xp;
    if (t == 0) xp = make_float4(0.f, 0.f, 0.f, 0.f);
    else        xp = *(const float4*)(x + i - CC);

    float4 k4 = *(const float4*)(mk + c);
    float4 v4 = *(const float4*)(mv + c);
    float4 r4 = *(const float4*)(mr + c);

    float4 o;
    o.x = xc.x*k4.x + xp.x*(1.f-k4.x); o.y = xc.y*k4.y + xp.y*(1.f-k4.y);
    o.z = xc.z*k4.z + xp.z*(1.f-k4.z); o.w = xc.w*k4.w + xp.w*(1.f-k4.w);
    pack4_store(o, g_xk + i);
    o.x = xc.x*v4.x + xp.x*(1.f-v4.x); o.y = xc.y*v4.y + xp.y*(1.f-v4.y);
    o.z = xc.z*v4.z + xp.z*(1.f-v4.z); o.w = xc.w*v4.w + xp.w*(1.f-v4.w);
    pack4_store(o, g_xv + i);
    o.x = xc.x*r4.x + xp.x*(1.f-r4.x); o.y = xc.y*r4.y + xp.y*(1.f-r4.y);
    o.z = xc.z*r4.z + xp.z*(1.f-r4.z); o.w = xc.w*r4.w + xp.w*(1.f-r4.w);
    pack4_store(o, g_xr + i);
}

// ---------------- 2) cp.async pipelined fp16 x2 GEMM ----------------
// C[M,N] = A[M,K] * (Bh+Bl)[N,K]^T ; tile 128x128, BK=64, 4 stages.
// Stage layout: [A 16K][B_hi 16K][B_lo 16K] = 48KB, SW128 swizzle.
#define STG_B  49152
#define STAGES 4
#define GEMM_SMEM (STAGES*STG_B)   // 196608

template<bool SIGMOID>
__global__ void __launch_bounds__(256, 1) gemm_fp16x2(
    const __half* __restrict__ A,
    const __half* __restrict__ Bh, const __half* __restrict__ Bl,
    float* __restrict__ C)
{
    extern __shared__ char smem[];
    const uint32_t sb0 = smem_u32(smem);

    const int tid = threadIdx.x;
    const int lid = tid & 31;
    const int wid = tid >> 5;
    const int warp_m = wid & 1;
    const int warp_n = wid >> 1;
    const int brow = blockIdx.y;
    const int bcol = blockIdx.x;

    // ---- cp.async assignment: 4 chunks of 16B per thread per 16KB tile ----
    const __half *pA[4], *pBh[4], *pBl[4];
    uint32_t sdst[4];
    #pragma unroll
    for (int j = 0; j < 4; j++) {
        int cid = tid + j * 256;
        int row = cid >> 3;
        int ch  = cid & 7;
        size_t aoff = ((size_t)(brow * 128 + row)) * CC + ch * 8;
        size_t boff = ((size_t)(bcol * 128 + row)) * CC + ch * 8;
        pA[j]  = A  + aoff;
        pBh[j] = Bh + boff;
        pBl[j] = Bl + boff;
        sdst[j] = (uint32_t)(row * 128 + ((ch ^ (row & 7)) << 4));
    }

    // ---- ldmatrix per-lane components ----
    const int a_row  = warp_m * 64 + ((lid >> 3) & 1) * 8 + (lid & 7);
    const int a_half = (lid >> 4) & 1;
    const uint32_t a_x = (uint32_t)(a_row & 7);
    const int b_row  = warp_n * 32 + (lid >> 4) * 8 + (lid & 7);
    const int b_half = (lid >> 3) & 1;
    const uint32_t b_x = (uint32_t)(b_row & 7);

    float acc[4][4][4];
    #pragma unroll
    for (int mt = 0; mt < 4; mt++)
        #pragma unroll
        for (int nt = 0; nt < 4; nt++)
            #pragma unroll
            for (int e = 0; e < 4; e++) acc[mt][nt][e] = 0.f;

    const int NK = CC / 64;   // 16

    #define LOAD_STAGE(S) do {                                          \
        uint32_t base = sb0 + (S) * STG_B;                              \
        _Pragma("unroll")                                               \
        for (int j = 0; j < 4; j++) {                                   \
            cpa16(base + sdst[j],          pA[j]);   pA[j]  += 64;      \
            cpa16(base + 16384 + sdst[j],  pBh[j]);  pBh[j] += 64;      \
            cpa16(base + 32768 + sdst[j],  pBl[j]);  pBl[j] += 64;      \
        }                                                               \
    } while (0)

    LOAD_STAGE(0); CP_COMMIT();
    LOAD_STAGE(1); CP_COMMIT();
    LOAD_STAGE(2); CP_COMMIT();

    for (int kc = 0; kc < NK; kc++) {
        CP_WAIT2();
        __syncthreads();
        if (kc + 3 < NK) {
            LOAD_STAGE((kc + 3) & 3);
        }
        CP_COMMIT();

        const uint32_t sA = sb0 + (kc & 3) * STG_B;
        const uint32_t sB = sA + 16384;

        #pragma unroll
        for (int ks = 0; ks < 4; ks++) {
            uint32_t bh[2][4], bl[2][4], ah[4][4];
            const uint32_t ac = ((uint32_t)(ks * 2 + a_half) ^ a_x) << 4;
            const uint32_t bc = ((uint32_t)(ks * 2 + b_half) ^ b_x) << 4;
            #pragma unroll
            for (int p = 0; p < 2; p++) {
                uint32_t addr = sB + (uint32_t)(b_row + p * 16) * 128 + bc;
                ldmx4(bh[p], addr);
                ldmx4(bl[p], addr + 16384);
            }
            #pragma unroll
            for (int mt = 0; mt < 4; mt++) {
                uint32_t addr = sA + (uint32_t)(a_row + mt * 16) * 128 + ac;
                ldmx4(ah[mt], addr);
            }
            #pragma unroll
            for (int mt = 0; mt < 4; mt++)
                #pragma unroll
                for (int nt = 0; nt < 4; nt++) {
                    int p = nt >> 1, q = (nt & 1) * 2;
                    mma_fp16(acc[mt][nt], ah[mt], bh[p][q], bh[p][q+1]);  // A*Bh
                    mma_fp16(acc[mt][nt], ah[mt], bl[p][q], bl[p][q+1]);  // A*Bl
                }
        }
    }
    #undef LOAD_STAGE

    // ---- epilogue ----
    const int r0 = (lid >> 2);
    const int c0 = (lid & 3) * 2;
    #pragma unroll
    for (int mt = 0; mt < 4; mt++) {
        size_t grow = (size_t)brow * 128 + warp_m * 64 + mt * 16 + r0;
        #pragma unroll
        for (int nt = 0; nt < 4; nt++) {
            int gcol = bcol * 128 + warp_n * 32 + nt * 8 + c0;
            float d0 = acc[mt][nt][0], d1 = acc[mt][nt][1];
            float d2 = acc[mt][nt][2], d3 = acc[mt][nt][3];
            if (SIGMOID) {
                d0 = fast_sigmoid(d0); d1 = fast_sigmoid(d1);
                d2 = fast_sigmoid(d2); d3 = fast_sigmoid(d3);
            }
            *(float2*)(C + grow * CC + gcol)       = make_float2(d0, d1);
            *(float2*)(C + (grow + 8) * CC + gcol) = make_float2(d2, d3);
        }
    }
}

// ---------------- 3) WKV: chunk-parallel 3-pass scan ----------------
__global__ void __launch_bounds__(256) wkv_pass1(const float* __restrict__ td)
{
    int gid = blockIdx.x * 256 + threadIdx.x;
    int c = gid & (CC - 1);
    int bj = gid >> 10;
    int b = bj >> 6;
    int j = bj & (NCH - 1);

    float w = -fast_exp(td[c]);
    float ew = fast_exp(w);

    size_t base = ((size_t)b * TT + (size_t)j * CHUNK) * CC + c;
    const float* kp = g_k + base;
    const float* vp = g_v + base;

    float A = 0.f, Bv = 0.f;
    for (int s = 0; s < CHUNK; s++) {
        float kt = kp[(size_t)s * CC];
        float vt = vp[(size_t)s * CC];
        float ek = fast_exp(kt);
        A = fmaf(A, ew, ek * vt);
        Bv = fmaf(Bv, ew, ek);
    }
    g_cA[gid] = A;
    g_cB[gid] = Bv;
}

__global__ void __launch_bounds__(256) wkv_combine(const float* __restrict__ td)
{
    int gid = blockIdx.x * 256 + threadIdx.x;
    if (gid >= BB * CC) return;
    int c = gid & (CC - 1);
    int b = gid >> 10;

    float w = -fast_exp(td[c]);
    float ewL = fast_exp(w * (float)CHUNK);

    float A = 0.f, Bv = 0.f;
    for (int j = 0; j < NCH; j++) {
        size_t idx = ((size_t)b * NCH + j) * CC + c;
        float ca = g_cA[idx], cb = g_cB[idx];
        g_cA[idx] = A;
        g_cB[idx] = Bv;
        A = fmaf(A, ewL, ca);
        Bv = fmaf(Bv, ewL, cb);
    }
}

__global__ void __launch_bounds__(256) wkv_pass2(const float* __restrict__ td,
                                                 const float* __restrict__ tf)
{
    int gid = blockIdx.x * 256 + threadIdx.x;
    int c = gid & (CC - 1);
    int bj = gid >> 10;
    int b = bj >> 6;
    int j = bj & (NCH - 1);

    float w = -fast_exp(td[c]);
    float ew = fast_exp(w);
    float eu = fast_exp(tf[c]);

    float A = g_cA[gid];
    float Bv = g_cB[gid];

    size_t base = ((size_t)b * TT + (size_t)j * CHUNK) * CC + c;
    const float* kp = g_k + base;
    const float* vp = g_v + base;
    const float* sp = g_sr + base;
    __half* op = g_rw + base;

    for (int s = 0; s < CHUNK; s++) {
        float kt = kp[(size_t)s * CC];
        float vt = vp[(size_t)s * CC];
        float st = sp[(size_t)s * CC];
        float ek = fast_exp(kt);
        float euk = eu * ek;
        float y = fmaf(euk, vt, A) * fast_rcp(Bv + euk);
        op[(size_t)s * CC] = __float2half_rn(st * y);
        A = fmaf(A, ew, ek * vt);
        Bv = fmaf(Bv, ew, ek);
    }
}

// ---------------- launch ----------------
extern "C" void kernel_launch(void* const* d_in, const int* in_sizes, int n_in,
                              void* d_out, int out_size)
{
    const float* x  = (const float*)d_in[0];
    const float* td = (const float*)d_in[1];
    const float* tf = (const float*)d_in[2];
    const float* mk = (const float*)d_in[3];
    const float* mv = (const float*)d_in[4];
    const float* mr = (const float*)d_in[5];
    const float* Wk = (const float*)d_in[6];
    const float* Wv = (const float*)d_in[7];
    const float* Wr = (const float*)d_in[8];
    const float* Wo = (const float*)d_in[9];
    float* out = (float*)d_out;

    __half *xk, *xv, *xr, *rw, *w_h, *w_l;
    float *p_k, *p_v, *p_sr;
    cudaGetSymbolAddress((void**)&xk,  g_xk);
    cudaGetSymbolAddress((void**)&xv,  g_xv);
    cudaGetSymbolAddress((void**)&xr,  g_xr);
    cudaGetSymbolAddress((void**)&rw,  g_rw);
    cudaGetSymbolAddress((void**)&w_h, g_w_h);
    cudaGetSymbolAddress((void**)&w_l, g_w_l);
    cudaGetSymbolAddress((void**)&p_k,  g_k);
    cudaGetSymbolAddress((void**)&p_v,  g_v);
    cudaGetSymbolAddress((void**)&p_sr, g_sr);

    cudaFuncSetAttribute(gemm_fp16x2<false>, cudaFuncAttributeMaxDynamicSharedMemorySize, GEMM_SMEM);
    cudaFuncSetAttribute(gemm_fp16x2<true>,  cudaFuncAttributeMaxDynamicSharedMemorySize, GEMM_SMEM);

    // 0) weight convert
    convert_w<<<(4*CC*CC/4 + 255) / 256, 256>>>(Wk, Wv, Wr, Wo);

    // 1) mix -> fp16
    {
        long long n4 = (long long)MT * CC / 4;
        mix_kernel<<<(int)((n4 + 255) / 256), 256>>>(x, mk, mv, mr);
    }

    // 2) projection GEMMs (sigmoid fused into r)
    dim3 gg(CC / 128, MT / 128);   // (8, 128)
    const int WSZ = CC * CC;
    gemm_fp16x2<false><<<gg, 256, GEMM_SMEM>>>(xk, w_h,         w_l,         p_k);
    gemm_fp16x2<false><<<gg, 256, GEMM_SMEM>>>(xv, w_h + WSZ,   w_l + WSZ,   p_v);
    gemm_fp16x2<true ><<<gg, 256, GEMM_SMEM>>>(xr, w_h + 2*WSZ, w_l + 2*WSZ, p_sr);

    // 3) WKV chunk-parallel scan
    {
        int n1 = BB * NCH * CC;
        wkv_pass1<<<n1 / 256, 256>>>(td);
        wkv_combine<<<(BB * CC + 255) / 256, 256>>>(td);
        wkv_pass2<<<n1 / 256, 256>>>(td, tf);
    }

    // 4) output GEMM
    gemm_fp16x2<false><<<gg, 256, GEMM_SMEM>>>(rw, w_h + 3*WSZ, w_l + 3*WSZ, out);
}

// round 6
// speedup vs baseline: 8.3432x; 1.1146x over previous
#include <cuda_runtime.h>
#include <cuda_fp16.h>
#include <cstdint>

#define BB 4
#define TT 4096
#define CC 1024
#define MT (BB*TT)          // 16384 rows
#define CHUNK 64
#define NCH (TT/CHUNK)      // 64 chunks

// ---------------- scratch (no cudaMalloc allowed) ----------------
__device__ __align__(128) __half g_xk[MT*CC];
__device__ __align__(128) __half g_xv[MT*CC];
__device__ __align__(128) __half g_xr[MT*CC];
__device__ __align__(128) __half g_rw[MT*CC];
__device__ __align__(128) __half g_w_h[4*CC*CC];
__device__ __align__(128) __half g_w_l[4*CC*CC];
__device__ float g_k [MT*CC];
__device__ float g_v [MT*CC];
__device__ float g_sr[MT*CC];
__device__ float g_cA[BB*NCH*CC];
__device__ float g_cB[BB*NCH*CC];

// ================= fast math (FMA-pipe, avoid MUFU) =================
__device__ __forceinline__ float fast_exp(float x) {
    float t = fmaf(x, 1.4426950408889634f, 12582912.0f);
    float n = t - 12582912.0f;
    float r = fmaf(x, 1.4426950408889634f, -n);
    float p = 1.3333558146e-3f;
    p = fmaf(p, r, 9.6181291076e-3f);
    p = fmaf(p, r, 5.5504108664e-2f);
    p = fmaf(p, r, 2.4022650696e-1f);
    p = fmaf(p, r, 6.9314718056e-1f);
    p = fmaf(p, r, 1.0f);
    int ei = (int)n;
    if (ei < -126) return 0.0f;
    if (ei > 127) ei = 127;
    return p * __int_as_float((ei + 127) << 23);
}

__device__ __forceinline__ float fast_rcp(float d) {
    float x = __int_as_float(0x7EF311C3 - __float_as_int(d));
    x = x * fmaf(-d, x, 2.0f);
    x = x * fmaf(-d, x, 2.0f);
    x = x * fmaf(-d, x, 2.0f);
    return x;
}

__device__ __forceinline__ float fast_sigmoid(float x) {
    return fast_rcp(1.0f + fast_exp(-x));
}

// ================= PTX helpers (arch-generic only) =================
__device__ __forceinline__ uint32_t smem_u32(const void* p) {
    uint32_t a;
    asm("{ .reg .u64 t; cvta.to.shared.u64 t, %1; cvt.u32.u64 %0, t; }" : "=r"(a) : "l"(p));
    return a;
}

__device__ __forceinline__ void ldmx4(uint32_t r[4], uint32_t addr) {
    asm volatile("ldmatrix.sync.aligned.m8n8.x4.shared.b16 {%0,%1,%2,%3}, [%4];"
        : "=r"(r[0]), "=r"(r[1]), "=r"(r[2]), "=r"(r[3]) : "r"(addr));
}

__device__ __forceinline__ void mma_fp16(float c[4], const uint32_t a[4],
                                         uint32_t b0, uint32_t b1) {
    asm volatile(
        "mma.sync.aligned.m16n8k16.row.col.f32.f16.f16.f32 "
        "{%0,%1,%2,%3}, {%4,%5,%6,%7}, {%8,%9}, {%0,%1,%2,%3};"
        : "+f"(c[0]), "+f"(c[1]), "+f"(c[2]), "+f"(c[3])
        : "r"(a[0]), "r"(a[1]), "r"(a[2]), "r"(a[3]), "r"(b0), "r"(b1));
}

__device__ __forceinline__ void cpa16(uint32_t dst, const void* src) {
    asm volatile("cp.async.cg.shared.global [%0], [%1], 16;" :: "r"(dst), "l"(src));
}
#define CP_COMMIT() asm volatile("cp.async.commit_group;" ::: "memory")
#define CP_WAIT1()  asm volatile("cp.async.wait_group 1;" ::: "memory")

// pack 4 fp32 -> 4 fp16 (8B)
__device__ __forceinline__ void pack4_store(float4 o, __half* p) {
    __half2 a = __floats2half2_rn(o.x, o.y);
    __half2 b = __floats2half2_rn(o.z, o.w);
    uint2 u;
    u.x = *(uint32_t*)&a;
    u.y = *(uint32_t*)&b;
    *(uint2*)p = u;
}

// ---------------- 0) weight convert (fp32 -> fp16 hi/lo) ----------------
__global__ void __launch_bounds__(256) convert_w(
    const float* __restrict__ Wk, const float* __restrict__ Wv,
    const float* __restrict__ Wr, const float* __restrict__ Wo)
{
    long long gid = (long long)blockIdx.x * 256 + threadIdx.x;
    long long i = gid * 4;
    if (i >= 4LL*CC*CC) return;
    int w = (int)(i >> 20);
    long long off = i & (CC*CC - 1);
    const float* src = (w == 0) ? Wk : (w == 1) ? Wv : (w == 2) ? Wr : Wo;
    float4 v = *(const float4*)(src + off);
    __half hx = __float2half_rn(v.x), hy = __float2half_rn(v.y);
    __half hz = __float2half_rn(v.z), hw = __float2half_rn(v.w);
    float4 lo = make_float4(v.x - __half2float(hx), v.y - __half2float(hy),
                            v.z - __half2float(hz), v.w - __half2float(hw));
    __half2 h01 = __halves2half2(hx, hy);
    __half2 h23 = __halves2half2(hz, hw);
    uint2 hu; hu.x = *(uint32_t*)&h01; hu.y = *(uint32_t*)&h23;
    *(uint2*)(g_w_h + i) = hu;
    pack4_store(lo, g_w_l + i);
}

// ---------------- 1) token-shift mix -> fp16 ----------------
__global__ void __launch_bounds__(256) mix_kernel(
    const float* __restrict__ x,
    const float* __restrict__ mk,
    const float* __restrict__ mv,
    const float* __restrict__ mr)
{
    long long idx = (long long)blockIdx.x * blockDim.x + threadIdx.x;
    long long i = idx * 4;
    if (i >= (long long)MT * CC) return;
    int c = (int)(i & (CC - 1));
    int m = (int)(i >> 10);
    int t = m & (TT - 1);

    float4 xc = *(const float4*)(x + i);
    float4 xp;
    if (t == 0) xp = make_float4(0.f, 0.f, 0.f, 0.f);
    else        xp = *(const float4*)(x + i - CC);

    float4 k4 = *(const float4*)(mk + c);
    float4 v4 = *(const float4*)(mv + c);
    float4 r4 = *(const float4*)(mr + c);

    float4 o;
    o.x = xc.x*k4.x + xp.x*(1.f-k4.x); o.y = xc.y*k4.y + xp.y*(1.f-k4.y);
    o.z = xc.z*k4.z + xp.z*(1.f-k4.z); o.w = xc.w*k4.w + xp.w*(1.f-k4.w);
    pack4_store(o, g_xk + i);
    o.x = xc.x*v4.x + xp.x*(1.f-v4.x); o.y = xc.y*v4.y + xp.y*(1.f-v4.y);
    o.z = xc.z*v4.z + xp.z*(1.f-v4.z); o.w = xc.w*v4.w + xp.w*(1.f-v4.w);
    pack4_store(o, g_xv + i);
    o.x = xc.x*r4.x + xp.x*(1.f-r4.x); o.y = xc.y*r4.y + xp.y*(1.f-r4.y);
    o.z = xc.z*r4.z + xp.z*(1.f-r4.z); o.w = xc.w*r4.w + xp.w*(1.f-r4.w);
    pack4_store(o, g_xr + i);
}

// ---------------- 2) cp.async pipelined fp16 x2 GEMM ----------------
// C[M,N] = A[M,K] * (Bh+Bl)[N,K]^T ; tile 128x128, BK=64, 2 stages, 2 CTAs/SM.
// Stage layout: [A 16K][B_hi 16K][B_lo 16K] = 48KB, SW128 swizzle.
#define STG_B  49152
#define GEMM_SMEM (2*STG_B)   // 98304 -> 2 CTAs/SM

template<bool SIGMOID>
__global__ void __launch_bounds__(256, 2) gemm_fp16x2(
    const __half* __restrict__ A,
    const __half* __restrict__ Bh, const __half* __restrict__ Bl,
    float* __restrict__ C)
{
    extern __shared__ char smem[];
    const uint32_t sb0 = smem_u32(smem);

    const int tid = threadIdx.x;
    const int lid = tid & 31;
    const int wid = tid >> 5;
    const int warp_m = wid & 1;
    const int warp_n = wid >> 1;
    const int brow = blockIdx.y;
    const int bcol = blockIdx.x;

    // ---- cp.async: 3 base pointers + derived offsets ----
    // thread's base chunk: row r0 = tid>>3 (0..31), ch = tid&7; chunk j adds 32 rows.
    const int r0 = tid >> 3;
    const int ch = tid & 7;
    const __half* bA  = A  + ((size_t)(brow * 128 + r0)) * CC + ch * 8;
    const __half* bBh = Bh + ((size_t)(bcol * 128 + r0)) * CC + ch * 8;
    const __half* bBl = Bl + ((size_t)(bcol * 128 + r0)) * CC + ch * 8;
    // swizzled smem offset for chunk 0; chunk j adds 32*128 = 4096 (XOR term invariant mod 8)
    const uint32_t sdst0 = (uint32_t)(r0 * 128 + ((ch ^ (r0 & 7)) << 4));

    // ---- ldmatrix per-lane components ----
    const int a_row  = warp_m * 64 + ((lid >> 3) & 1) * 8 + (lid & 7);
    const int a_half = (lid >> 4) & 1;
    const uint32_t a_x = (uint32_t)(a_row & 7);
    const int b_row  = warp_n * 32 + (lid >> 4) * 8 + (lid & 7);
    const int b_half = (lid >> 3) & 1;
    const uint32_t b_x = (uint32_t)(b_row & 7);

    float acc[4][4][4];
    #pragma unroll
    for (int mt = 0; mt < 4; mt++)
        #pragma unroll
        for (int nt = 0; nt < 4; nt++)
            #pragma unroll
            for (int e = 0; e < 4; e++) acc[mt][nt][e] = 0.f;

    const int NK = CC / 64;   // 16

    // load one stage; kc'th call reads columns [kc*64, kc*64+64)
    #define LOAD_STAGE(S, KC) do {                                            \
        uint32_t base = sb0 + (S) * STG_B + sdst0;                            \
        const __half* sA  = bA  + (KC) * 64;                                  \
        const __half* sBh = bBh + (KC) * 64;                                  \
        const __half* sBl = bBl + (KC) * 64;                                  \
        _Pragma("unroll")                                                     \
        for (int j = 0; j < 4; j++) {                                         \
            cpa16(base + j*4096,          sA  + (size_t)j * (32*CC));         \
            cpa16(base + 16384 + j*4096,  sBh + (size_t)j * (32*CC));         \
            cpa16(base + 32768 + j*4096,  sBl + (size_t)j * (32*CC));         \
        }                                                                     \
    } while (0)

    LOAD_STAGE(0, 0); CP_COMMIT();
    LOAD_STAGE(1, 1); CP_COMMIT();

    for (int kc = 0; kc < NK; kc++) {
        CP_WAIT1();          // stage kc resident
        __syncthreads();

        const uint32_t sA = sb0 + (kc & 1) * STG_B;
        const uint32_t sB = sA + 16384;

        #pragma unroll
        for (int ks = 0; ks < 4; ks++) {
            uint32_t ah[4][4];
            const uint32_t ac = ((uint32_t)(ks * 2 + a_half) ^ a_x) << 4;
            const uint32_t bc = ((uint32_t)(ks * 2 + b_half) ^ b_x) << 4;
            #pragma unroll
            for (int mt = 0; mt < 4; mt++)
                ldmx4(ah[mt], sA + (uint32_t)(a_row + mt * 16) * 128 + ac);
            #pragma unroll
            for (int p = 0; p < 2; p++) {
                uint32_t bh[4], bl[4];
                uint32_t addr = sB + (uint32_t)(b_row + p * 16) * 128 + bc;
                ldmx4(bh, addr);
                ldmx4(bl, addr + 16384);
                #pragma unroll
                for (int mt = 0; mt < 4; mt++)
                    #pragma unroll
                    for (int n2 = 0; n2 < 2; n2++) {
                        int nt = p * 2 + n2, q = n2 * 2;
                        mma_fp16(acc[mt][nt], ah[mt], bh[q], bh[q+1]);
                        mma_fp16(acc[mt][nt], ah[mt], bl[q], bl[q+1]);
                    }
            }
        }

        __syncthreads();     // all warps done reading stage before overwrite
        if (kc + 2 < NK) {
            LOAD_STAGE(kc & 1, kc + 2);
        }
        CP_COMMIT();
    }
    #undef LOAD_STAGE

    // ---- epilogue ----
    const int er = (lid >> 2);
    const int ec = (lid & 3) * 2;
    #pragma unroll
    for (int mt = 0; mt < 4; mt++) {
        size_t grow = (size_t)brow * 128 + warp_m * 64 + mt * 16 + er;
        #pragma unroll
        for (int nt = 0; nt < 4; nt++) {
            int gcol = bcol * 128 + warp_n * 32 + nt * 8 + ec;
            float d0 = acc[mt][nt][0], d1 = acc[mt][nt][1];
            float d2 = acc[mt][nt][2], d3 = acc[mt][nt][3];
            if (SIGMOID) {
                d0 = fast_sigmoid(d0); d1 = fast_sigmoid(d1);
                d2 = fast_sigmoid(d2); d3 = fast_sigmoid(d3);
            }
            *(float2*)(C + grow * CC + gcol)       = make_float2(d0, d1);
            *(float2*)(C + (grow + 8) * CC + gcol) = make_float2(d2, d3);
        }
    }
}

// ---------------- 3) WKV: chunk-parallel 3-pass scan ----------------
__global__ void __launch_bounds__(256) wkv_pass1(const float* __restrict__ td)
{
    int gid = blockIdx.x * 256 + threadIdx.x;
    int c = gid & (CC - 1);
    int bj = gid >> 10;
    int b = bj >> 6;
    int j = bj & (NCH - 1);

    float w = -fast_exp(td[c]);
    float ew = fast_exp(w);

    size_t base = ((size_t)b * TT + (size_t)j * CHUNK) * CC + c;
    const float* kp = g_k + base;
    const float* vp = g_v + base;

    float A = 0.f, Bv = 0.f;
    for (int s = 0; s < CHUNK; s++) {
        float kt = kp[(size_t)s * CC];
        float vt = vp[(size_t)s * CC];
        float ek = fast_exp(kt);
        A = fmaf(A, ew, ek * vt);
        Bv = fmaf(Bv, ew, ek);
    }
    g_cA[gid] = A;
    g_cB[gid] = Bv;
}

__global__ void __launch_bounds__(256) wkv_combine(const float* __restrict__ td)
{
    int gid = blockIdx.x * 256 + threadIdx.x;
    if (gid >= BB * CC) return;
    int c = gid & (CC - 1);
    int b = gid >> 10;

    float w = -fast_exp(td[c]);
    float ewL = fast_exp(w * (float)CHUNK);

    float A = 0.f, Bv = 0.f;
    for (int j = 0; j < NCH; j++) {
        size_t idx = ((size_t)b * NCH + j) * CC + c;
        float ca = g_cA[idx], cb = g_cB[idx];
        g_cA[idx] = A;
        g_cB[idx] = Bv;
        A = fmaf(A, ewL, ca);
        Bv = fmaf(Bv, ewL, cb);
    }
}

__global__ void __launch_bounds__(256) wkv_pass2(const float* __restrict__ td,
                                                 const float* __restrict__ tf)
{
    int gid = blockIdx.x * 256 + threadIdx.x;
    int c = gid & (CC - 1);
    int bj = gid >> 10;
    int b = bj >> 6;
    int j = bj & (NCH - 1);

    float w = -fast_exp(td[c]);
    float ew = fast_exp(w);
    float eu = fast_exp(tf[c]);

    float A = g_cA[gid];
    float Bv = g_cB[gid];

    size_t base = ((size_t)b * TT + (size_t)j * CHUNK) * CC + c;
    const float* kp = g_k + base;
    const float* vp = g_v + base;
    const float* sp = g_sr + base;
    __half* op = g_rw + base;

    for (int s = 0; s < CHUNK; s++) {
        float kt = kp[(size_t)s * CC];
        float vt = vp[(size_t)s * CC];
        float st = sp[(size_t)s * CC];
        float ek = fast_exp(kt);
        float euk = eu * ek;
        float y = fmaf(euk, vt, A) * fast_rcp(Bv + euk);
        op[(size_t)s * CC] = __float2half_rn(st * y);
        A = fmaf(A, ew, ek * vt);
        Bv = fmaf(Bv, ew, ek);
    }
}

// ---------------- launch ----------------
extern "C" void kernel_launch(void* const* d_in, const int* in_sizes, int n_in,
                              void* d_out, int out_size)
{
    const float* x  = (const float*)d_in[0];
    const float* td = (const float*)d_in[1];
    const float* tf = (const float*)d_in[2];
    const float* mk = (const float*)d_in[3];
    const float* mv = (const float*)d_in[4];
    const float* mr = (const float*)d_in[5];
    const float* Wk = (const float*)d_in[6];
    const float* Wv = (const float*)d_in[7];
    const float* Wr = (const float*)d_in[8];
    const float* Wo = (const float*)d_in[9];
    float* out = (float*)d_out;

    __half *xk, *xv, *xr, *rw, *w_h, *w_l;
    float *p_k, *p_v, *p_sr;
    cudaGetSymbolAddress((void**)&xk,  g_xk);
    cudaGetSymbolAddress((void**)&xv,  g_xv);
    cudaGetSymbolAddress((void**)&xr,  g_xr);
    cudaGetSymbolAddress((void**)&rw,  g_rw);
    cudaGetSymbolAddress((void**)&w_h, g_w_h);
    cudaGetSymbolAddress((void**)&w_l, g_w_l);
    cudaGetSymbolAddress((void**)&p_k,  g_k);
    cudaGetSymbolAddress((void**)&p_v,  g_v);
    cudaGetSymbolAddress((void**)&p_sr, g_sr);

    cudaFuncSetAttribute(gemm_fp16x2<false>, cudaFuncAttributeMaxDynamicSharedMemorySize, GEMM_SMEM);
    cudaFuncSetAttribute(gemm_fp16x2<true>,  cudaFuncAttributeMaxDynamicSharedMemorySize, GEMM_SMEM);

    // 0) weight convert
    convert_w<<<(4*CC*CC/4 + 255) / 256, 256>>>(Wk, Wv, Wr, Wo);

    // 1) mix -> fp16
    {
        long long n4 = (long long)MT * CC / 4;
        mix_kernel<<<(int)((n4 + 255) / 256), 256>>>(x, mk, mv, mr);
    }

    // 2) projection GEMMs (sigmoid fused into r)
    dim3 gg(CC / 128, MT / 128);   // (8, 128)
    const int WSZ = CC * CC;
    gemm_fp16x2<false><<<gg, 256, GEMM_SMEM>>>(xk, w_h,         w_l,         p_k);
    gemm_fp16x2<false><<<gg, 256, GEMM_SMEM>>>(xv, w_h + WSZ,   w_l + WSZ,   p_v);
    gemm_fp16x2<true ><<<gg, 256, GEMM_SMEM>>>(xr, w_h + 2*WSZ, w_l + 2*WSZ, p_sr);

    // 3) WKV chunk-parallel scan
    {
        int n1 = BB * NCH * CC;
        wkv_pass1<<<n1 / 256, 256>>>(td);
        wkv_combine<<<(BB * CC + 255) / 256, 256>>>(td);
        wkv_pass2<<<n1 / 256, 256>>>(td, tf);
    }

    // 4) output GEMM
    gemm_fp16x2<false><<<gg, 256, GEMM_SMEM>>>(rw, w_h + 3*WSZ, w_l + 3*WSZ, out);
}

// round 7
// speedup vs baseline: 12.8568x; 1.5410x over previous
#include <cuda_runtime.h>
#include <cuda_fp16.h>
#include <cstdint>

#define BB 4
#define TT 4096
#define CC 1024
#define MT (BB*TT)          // 16384 rows
#define CHUNK 64
#define NCH (TT/CHUNK)      // 64 chunks

// ---------------- scratch (no cudaMalloc allowed) ----------------
__device__ __align__(128) __half g_xk[MT*CC];
__device__ __align__(128) __half g_xv[MT*CC];
__device__ __align__(128) __half g_xr[MT*CC];
__device__ __align__(128) __half g_rw[MT*CC];
__device__ __align__(128) __half g_w[4*CC*CC];
__device__ float g_k [MT*CC];
__device__ float g_v [MT*CC];
__device__ float g_sr[MT*CC];
__device__ float g_cA[BB*NCH*CC];
__device__ float g_cB[BB*NCH*CC];

// ================= fast math (FMA-pipe, avoid MUFU) =================
__device__ __forceinline__ float fast_exp(float x) {
    float t = fmaf(x, 1.4426950408889634f, 12582912.0f);
    float n = t - 12582912.0f;
    float r = fmaf(x, 1.4426950408889634f, -n);
    float p = 1.3333558146e-3f;
    p = fmaf(p, r, 9.6181291076e-3f);
    p = fmaf(p, r, 5.5504108664e-2f);
    p = fmaf(p, r, 2.4022650696e-1f);
    p = fmaf(p, r, 6.9314718056e-1f);
    p = fmaf(p, r, 1.0f);
    int ei = (int)n;
    if (ei < -126) return 0.0f;
    if (ei > 127) ei = 127;
    return p * __int_as_float((ei + 127) << 23);
}

__device__ __forceinline__ float fast_rcp(float d) {
    float x = __int_as_float(0x7EF311C3 - __float_as_int(d));
    x = x * fmaf(-d, x, 2.0f);
    x = x * fmaf(-d, x, 2.0f);
    x = x * fmaf(-d, x, 2.0f);
    return x;
}

__device__ __forceinline__ float fast_sigmoid(float x) {
    return fast_rcp(1.0f + fast_exp(-x));
}

// ================= PTX helpers (arch-generic only) =================
__device__ __forceinline__ uint32_t smem_u32(const void* p) {
    uint32_t a;
    asm("{ .reg .u64 t; cvta.to.shared.u64 t, %1; cvt.u32.u64 %0, t; }" : "=r"(a) : "l"(p));
    return a;
}

__device__ __forceinline__ void ldmx4(uint32_t r[4], uint32_t addr) {
    asm volatile("ldmatrix.sync.aligned.m8n8.x4.shared.b16 {%0,%1,%2,%3}, [%4];"
        : "=r"(r[0]), "=r"(r[1]), "=r"(r[2]), "=r"(r[3]) : "r"(addr));
}

__device__ __forceinline__ void mma_fp16(float c[4], const uint32_t a[4],
                                         uint32_t b0, uint32_t b1) {
    asm volatile(
        "mma.sync.aligned.m16n8k16.row.col.f32.f16.f16.f32 "
        "{%0,%1,%2,%3}, {%4,%5,%6,%7}, {%8,%9}, {%0,%1,%2,%3};"
        : "+f"(c[0]), "+f"(c[1]), "+f"(c[2]), "+f"(c[3])
        : "r"(a[0]), "r"(a[1]), "r"(a[2]), "r"(a[3]), "r"(b0), "r"(b1));
}

__device__ __forceinline__ void cpa16(uint32_t dst, const void* src) {
    asm volatile("cp.async.cg.shared.global [%0], [%1], 16;" :: "r"(dst), "l"(src));
}
#define CP_COMMIT() asm volatile("cp.async.commit_group;" ::: "memory")
#define CP_WAIT1()  asm volatile("cp.async.wait_group 1;" ::: "memory")

// pack 4 fp32 -> 4 fp16 (8B)
__device__ __forceinline__ void pack4_store(float4 o, __half* p) {
    __half2 a = __floats2half2_rn(o.x, o.y);
    __half2 b = __floats2half2_rn(o.z, o.w);
    uint2 u;
    u.x = *(uint32_t*)&a;
    u.y = *(uint32_t*)&b;
    *(uint2*)p = u;
}

// ---------------- 0) weight convert (fp32 -> fp16) ----------------
__global__ void __launch_bounds__(256) convert_w(
    const float* __restrict__ Wk, const float* __restrict__ Wv,
    const float* __restrict__ Wr, const float* __restrict__ Wo)
{
    long long gid = (long long)blockIdx.x * 256 + threadIdx.x;
    long long i = gid * 4;
    if (i >= 4LL*CC*CC) return;
    int w = (int)(i >> 20);
    long long off = i & (CC*CC - 1);
    const float* src = (w == 0) ? Wk : (w == 1) ? Wv : (w == 2) ? Wr : Wo;
    float4 v = *(const float4*)(src + off);
    pack4_store(v, g_w + i);
}

// ---------------- 1) token-shift mix -> fp16 ----------------
__global__ void __launch_bounds__(256) mix_kernel(
    const float* __restrict__ x,
    const float* __restrict__ mk,
    const float* __restrict__ mv,
    const float* __restrict__ mr)
{
    long long idx = (long long)blockIdx.x * blockDim.x + threadIdx.x;
    long long i = idx * 4;
    if (i >= (long long)MT * CC) return;
    int c = (int)(i & (CC - 1));
    int m = (int)(i >> 10);
    int t = m & (TT - 1);

    float4 xc = *(const float4*)(x + i);
    float4 xp;
    if (t == 0) xp = make_float4(0.f, 0.f, 0.f, 0.f);
    else        xp = *(const float4*)(x + i - CC);

    float4 k4 = *(const float4*)(mk + c);
    float4 v4 = *(const float4*)(mv + c);
    float4 r4 = *(const float4*)(mr + c);

    float4 o;
    o.x = xc.x*k4.x + xp.x*(1.f-k4.x); o.y = xc.y*k4.y + xp.y*(1.f-k4.y);
    o.z = xc.z*k4.z + xp.z*(1.f-k4.z); o.w = xc.w*k4.w + xp.w*(1.f-k4.w);
    pack4_store(o, g_xk + i);
    o.x = xc.x*v4.x + xp.x*(1.f-v4.x); o.y = xc.y*v4.y + xp.y*(1.f-v4.y);
    o.z = xc.z*v4.z + xp.z*(1.f-v4.z); o.w = xc.w*v4.w + xp.w*(1.f-v4.w);
    pack4_store(o, g_xv + i);
    o.x = xc.x*r4.x + xp.x*(1.f-r4.x); o.y = xc.y*r4.y + xp.y*(1.f-r4.y);
    o.z = xc.z*r4.z + xp.z*(1.f-r4.z); o.w = xc.w*r4.w + xp.w*(1.f-r4.w);
    pack4_store(o, g_xr + i);
}

// ---------------- 2) cp.async pipelined fp16 GEMM ----------------
// C[M,N] = A[M,K] * B[N,K]^T ; tile 128x128, BK=64, 3 stages, 2 CTAs/SM.
// Stage layout: [A 16K][B 16K] = 32KB, SW128 swizzle.
#define STG_B  32768
#define GEMM_SMEM (3*STG_B)   // 98304 -> 2 CTAs/SM

template<bool SIGMOID>
__global__ void __launch_bounds__(256, 2) gemm_fp16(
    const __half* __restrict__ A,
    const __half* __restrict__ B,
    float* __restrict__ C)
{
    extern __shared__ char smem[];
    const uint32_t sb0 = smem_u32(smem);

    const int tid = threadIdx.x;
    const int lid = tid & 31;
    const int wid = tid >> 5;
    const int warp_m = wid & 1;
    const int warp_n = wid >> 1;
    const int brow = blockIdx.y;
    const int bcol = blockIdx.x;

    // ---- cp.async: base pointers + derived offsets ----
    const int r0 = tid >> 3;
    const int ch = tid & 7;
    const __half* bA = A + ((size_t)(brow * 128 + r0)) * CC + ch * 8;
    const __half* bB = B + ((size_t)(bcol * 128 + r0)) * CC + ch * 8;
    const uint32_t sdst0 = (uint32_t)(r0 * 128 + ((ch ^ (r0 & 7)) << 4));

    // ---- ldmatrix per-lane components ----
    const int a_row  = warp_m * 64 + ((lid >> 3) & 1) * 8 + (lid & 7);
    const int a_half = (lid >> 4) & 1;
    const uint32_t a_x = (uint32_t)(a_row & 7);
    const int b_row  = warp_n * 32 + (lid >> 4) * 8 + (lid & 7);
    const int b_half = (lid >> 3) & 1;
    const uint32_t b_x = (uint32_t)(b_row & 7);

    float acc[4][4][4];
    #pragma unroll
    for (int mt = 0; mt < 4; mt++)
        #pragma unroll
        for (int nt = 0; nt < 4; nt++)
            #pragma unroll
            for (int e = 0; e < 4; e++) acc[mt][nt][e] = 0.f;

    const int NK = CC / 64;   // 16

    #define LOAD_STAGE(S, KC) do {                                            \
        uint32_t base = sb0 + (S) * STG_B + sdst0;                            \
        const __half* sAp = bA + (KC) * 64;                                   \
        const __half* sBp = bB + (KC) * 64;                                   \
        _Pragma("unroll")                                                     \
        for (int j = 0; j < 4; j++) {                                         \
            cpa16(base + j*4096,          sAp + (size_t)j * (32*CC));         \
            cpa16(base + 16384 + j*4096,  sBp + (size_t)j * (32*CC));         \
        }                                                                     \
    } while (0)

    LOAD_STAGE(0, 0); CP_COMMIT();
    LOAD_STAGE(1, 1); CP_COMMIT();

    int cs = 0;      // stage holding data for current kc
    int ls = 2;      // stage to load into (consumed two iterations ago)
    for (int kc = 0; kc < NK; kc++) {
        CP_WAIT1();          // stage cs resident
        __syncthreads();

        if (kc + 2 < NK) {
            LOAD_STAGE(ls, kc + 2);
        }
        CP_COMMIT();

        const uint32_t sA = sb0 + cs * STG_B;
        const uint32_t sB = sA + 16384;

        #pragma unroll
        for (int ks = 0; ks < 4; ks++) {
            uint32_t ah[4][4];
            const uint32_t ac = ((uint32_t)(ks * 2 + a_half) ^ a_x) << 4;
            const uint32_t bc = ((uint32_t)(ks * 2 + b_half) ^ b_x) << 4;
            #pragma unroll
            for (int mt = 0; mt < 4; mt++)
                ldmx4(ah[mt], sA + (uint32_t)(a_row + mt * 16) * 128 + ac);
            #pragma unroll
            for (int p = 0; p < 2; p++) {
                uint32_t bh[4];
                ldmx4(bh, sB + (uint32_t)(b_row + p * 16) * 128 + bc);
                #pragma unroll
                for (int mt = 0; mt < 4; mt++)
                    #pragma unroll
                    for (int n2 = 0; n2 < 2; n2++)
                        mma_fp16(acc[mt][p*2 + n2], ah[mt], bh[n2*2], bh[n2*2 + 1]);
            }
        }

        cs = (cs == 2) ? 0 : cs + 1;
        ls = (ls == 2) ? 0 : ls + 1;
    }
    #undef LOAD_STAGE

    // ---- epilogue ----
    const int er = (lid >> 2);
    const int ec = (lid & 3) * 2;
    #pragma unroll
    for (int mt = 0; mt < 4; mt++) {
        size_t grow = (size_t)brow * 128 + warp_m * 64 + mt * 16 + er;
        #pragma unroll
        for (int nt = 0; nt < 4; nt++) {
            int gcol = bcol * 128 + warp_n * 32 + nt * 8 + ec;
            float d0 = acc[mt][nt][0], d1 = acc[mt][nt][1];
            float d2 = acc[mt][nt][2], d3 = acc[mt][nt][3];
            if (SIGMOID) {
                d0 = fast_sigmoid(d0); d1 = fast_sigmoid(d1);
                d2 = fast_sigmoid(d2); d3 = fast_sigmoid(d3);
            }
            *(float2*)(C + grow * CC + gcol)       = make_float2(d0, d1);
            *(float2*)(C + (grow + 8) * CC + gcol) = make_float2(d2, d3);
        }
    }
}

// ---------------- 3) WKV: chunk-parallel 3-pass scan ----------------
__global__ void __launch_bounds__(256) wkv_pass1(const float* __restrict__ td)
{
    int gid = blockIdx.x * 256 + threadIdx.x;
    int c = gid & (CC - 1);
    int bj = gid >> 10;
    int b = bj >> 6;
    int j = bj & (NCH - 1);

    float w = -fast_exp(td[c]);
    float ew = fast_exp(w);

    size_t base = ((size_t)b * TT + (size_t)j * CHUNK) * CC + c;
    const float* kp = g_k + base;
    const float* vp = g_v + base;

    float A = 0.f, Bv = 0.f;
    for (int s = 0; s < CHUNK; s++) {
        float kt = kp[(size_t)s * CC];
        float vt = vp[(size_t)s * CC];
        float ek = fast_exp(kt);
        A = fmaf(A, ew, ek * vt);
        Bv = fmaf(Bv, ew, ek);
    }
    g_cA[gid] = A;
    g_cB[gid] = Bv;
}

__global__ void __launch_bounds__(256) wkv_combine(const float* __restrict__ td)
{
    int gid = blockIdx.x * 256 + threadIdx.x;
    if (gid >= BB * CC) return;
    int c = gid & (CC - 1);
    int b = gid >> 10;

    float w = -fast_exp(td[c]);
    float ewL = fast_exp(w * (float)CHUNK);

    float A = 0.f, Bv = 0.f;
    for (int j = 0; j < NCH; j++) {
        size_t idx = ((size_t)b * NCH + j) * CC + c;
        float ca = g_cA[idx], cb = g_cB[idx];
        g_cA[idx] = A;
        g_cB[idx] = Bv;
        A = fmaf(A, ewL, ca);
        Bv = fmaf(Bv, ewL, cb);
    }
}

__global__ void __launch_bounds__(256) wkv_pass2(const float* __restrict__ td,
                                                 const float* __restrict__ tf)
{
    int gid = blockIdx.x * 256 + threadIdx.x;
    int c = gid & (CC - 1);
    int bj = gid >> 10;
    int b = bj >> 6;
    int j = bj & (NCH - 1);

    float w = -fast_exp(td[c]);
    float ew = fast_exp(w);
    float eu = fast_exp(tf[c]);

    float A = g_cA[gid];
    float Bv = g_cB[gid];

    size_t base = ((size_t)b * TT + (size_t)j * CHUNK) * CC + c;
    const float* kp = g_k + base;
    const float* vp = g_v + base;
    const float* sp = g_sr + base;
    __half* op = g_rw + base;

    for (int s = 0; s < CHUNK; s++) {
        float kt = kp[(size_t)s * CC];
        float vt = vp[(size_t)s * CC];
        float st = sp[(size_t)s * CC];
        float ek = fast_exp(kt);
        float euk = eu * ek;
        float y = fmaf(euk, vt, A) * fast_rcp(Bv + euk);
        op[(size_t)s * CC] = __float2half_rn(st * y);
        A = fmaf(A, ew, ek * vt);
        Bv = fmaf(Bv, ew, ek);
    }
}

// ---------------- launch ----------------
extern "C" void kernel_launch(void* const* d_in, const int* in_sizes, int n_in,
                              void* d_out, int out_size)
{
    const float* x  = (const float*)d_in[0];
    const float* td = (const float*)d_in[1];
    const float* tf = (const float*)d_in[2];
    const float* mk = (const float*)d_in[3];
    const float* mv = (const float*)d_in[4];
    const float* mr = (const float*)d_in[5];
    const float* Wk = (const float*)d_in[6];
    const float* Wv = (const float*)d_in[7];
    const float* Wr = (const float*)d_in[8];
    const float* Wo = (const float*)d_in[9];
    float* out = (float*)d_out;

    __half *xk, *xv, *xr, *rw, *w;
    float *p_k, *p_v, *p_sr;
    cudaGetSymbolAddress((void**)&xk, g_xk);
    cudaGetSymbolAddress((void**)&xv, g_xv);
    cudaGetSymbolAddress((void**)&xr, g_xr);
    cudaGetSymbolAddress((void**)&rw, g_rw);
    cudaGetSymbolAddress((void**)&w,  g_w);
    cudaGetSymbolAddress((void**)&p_k,  g_k);
    cudaGetSymbolAddress((void**)&p_v,  g_v);
    cudaGetSymbolAddress((void**)&p_sr, g_sr);

    cudaFuncSetAttribute(gemm_fp16<false>, cudaFuncAttributeMaxDynamicSharedMemorySize, GEMM_SMEM);
    cudaFuncSetAttribute(gemm_fp16<true>,  cudaFuncAttributeMaxDynamicSharedMemorySize, GEMM_SMEM);

    // 0) weight convert
    convert_w<<<(4*CC*CC/4 + 255) / 256, 256>>>(Wk, Wv, Wr, Wo);

    // 1) mix -> fp16
    {
        long long n4 = (long long)MT * CC / 4;
        mix_kernel<<<(int)((n4 + 255) / 256), 256>>>(x, mk, mv, mr);
    }

    // 2) projection GEMMs (sigmoid fused into r)
    dim3 gg(CC / 128, MT / 128);   // (8, 128)
    const int WSZ = CC * CC;
    gemm_fp16<false><<<gg, 256, GEMM_SMEM>>>(xk, w,         p_k);
    gemm_fp16<false><<<gg, 256, GEMM_SMEM>>>(xv, w + WSZ,   p_v);
    gemm_fp16<true ><<<gg, 256, GEMM_SMEM>>>(xr, w + 2*WSZ, p_sr);

    // 3) WKV chunk-parallel scan
    {
        int n1 = BB * NCH * CC;
        wkv_pass1<<<n1 / 256, 256>>>(td);
        wkv_combine<<<(BB * CC + 255) / 256, 256>>>(td);
        wkv_pass2<<<n1 / 256, 256>>>(td, tf);
    }

    // 4) output GEMM
    gemm_fp16<false><<<gg, 256, GEMM_SMEM>>>(rw, w + 3*WSZ, out);
}